// round 5
// baseline (speedup 1.0000x reference)
#include <cuda_runtime.h>
#include <cuda_bf16.h>
#include <cstdint>

// Problem constants (fixed shapes)
#define BATCH 2
#define SEQ   2048
#define DMODEL 2048
#define NH    32
#define NKV   8
#define HD    64
#define NTOK  (BATCH*SEQ)          // 4096

// ---------------- f32x2 packed math helpers ----------------
__device__ __forceinline__ void fma2(unsigned long long &d, unsigned long long a, unsigned long long b) {
    asm("fma.rn.f32x2 %0, %1, %2, %0;" : "+l"(d) : "l"(a), "l"(b));
}
__device__ __forceinline__ unsigned long long mul2(unsigned long long a, unsigned long long b) {
    unsigned long long r;
    asm("mul.rn.f32x2 %0, %1, %2;" : "=l"(r) : "l"(a), "l"(b));
    return r;
}
__device__ __forceinline__ unsigned long long pack2(float lo, float hi) {
    unsigned long long r;
    asm("mov.b64 %0, {%1, %2};" : "=l"(r) : "f"(lo), "f"(hi));
    return r;
}
__device__ __forceinline__ void unpack2(unsigned long long v, float &lo, float &hi) {
    asm("mov.b64 {%0, %1}, %2;" : "=f"(lo), "=f"(hi) : "l"(v));
}

// ---------------- mma.sync / ldmatrix helpers ----------------
__device__ __forceinline__ void ldsm4(uint32_t &r0, uint32_t &r1, uint32_t &r2, uint32_t &r3, uint32_t addr) {
    asm volatile("ldmatrix.sync.aligned.m8n8.x4.shared.b16 {%0,%1,%2,%3}, [%4];"
                 : "=r"(r0), "=r"(r1), "=r"(r2), "=r"(r3) : "r"(addr));
}
__device__ __forceinline__ void imma16832(int* c, const uint32_t* a, const uint32_t* b) {
    asm volatile("mma.sync.aligned.m16n8k32.row.col.s32.s8.s8.s32 "
                 "{%0,%1,%2,%3}, {%4,%5,%6,%7}, {%8,%9}, {%0,%1,%2,%3};"
                 : "+r"(c[0]), "+r"(c[1]), "+r"(c[2]), "+r"(c[3])
                 : "r"(a[0]), "r"(a[1]), "r"(a[2]), "r"(a[3]), "r"(b[0]), "r"(b[1]));
}

// ---------------- device scratch (static, allocation-free) ----------------
__device__ float g_partial[4*256];
__device__ float g_wscale[4];
__device__ __align__(16) signed char g_wq[DMODEL*DMODEL];
__device__ __align__(16) signed char g_wk[NKV*HD*DMODEL];
__device__ __align__(16) signed char g_wv[NKV*HD*DMODEL];
__device__ __align__(16) signed char g_wo[DMODEL*DMODEL];
__device__ __align__(16) signed char g_xq0[NTOK*DMODEL];
__device__ __align__(16) signed char g_xq1[NTOK*DMODEL];
__device__ __align__(16) signed char g_xq2[NTOK*DMODEL];
__device__ __align__(16) signed char g_xqo[NTOK*DMODEL];
__device__ float g_xs0[NTOK];
__device__ float g_xs1[NTOK];
__device__ float g_xs2[NTOK];
__device__ float g_xso[NTOK];
__device__ float g_projq[NTOK*DMODEL];     // [token, h*64+d]
__device__ float g_projk[NTOK*NKV*HD];     // [token, kv*64+d]
__device__ float g_projv[NTOK*NKV*HD];
__device__ float g_attn[NTOK*DMODEL];      // [token, h*64+d]

// ---------------- weight abs-mean (deterministic 2-pass) ----------------
__global__ void absum_partial(const float* __restrict__ w, int n, int k) {
    __shared__ float red[256];
    int tid = threadIdx.x;
    float s = 0.f;
    for (int i = blockIdx.x*256 + tid; i < n; i += 256*256) s += fabsf(w[i]);
    red[tid] = s; __syncthreads();
    for (int st = 128; st > 0; st >>= 1) { if (tid < st) red[tid] += red[tid+st]; __syncthreads(); }
    if (tid == 0) g_partial[k*256 + blockIdx.x] = red[0];
}

__global__ void finalize_wscale() {
    __shared__ float red[256];
    int tid = threadIdx.x;
    const float ninv[4] = {1.f/(2048.f*2048.f), 1.f/(512.f*2048.f),
                           1.f/(512.f*2048.f), 1.f/(2048.f*2048.f)};
    for (int k = 0; k < 4; k++) {
        red[tid] = g_partial[k*256 + tid]; __syncthreads();
        for (int st = 128; st > 0; st >>= 1) { if (tid < st) red[tid] += red[tid+st]; __syncthreads(); }
        if (tid == 0) g_wscale[k] = fmaxf(red[0]*ninv[k], 1e-5f);
        __syncthreads();
    }
}

__global__ void quant_w(const float* __restrict__ w, signed char* __restrict__ wq, int n, int widx) {
    float inv = 1.f / g_wscale[widx];
    for (int i = blockIdx.x*blockDim.x + threadIdx.x; i < n; i += gridDim.x*blockDim.x) {
        float q = rintf(w[i]*inv);
        q = fminf(fmaxf(q, -1.f), 1.f);
        wq[i] = (signed char)q;
    }
}

// ---------------- activation quant (rmsnorm + absmax int8), up to 3 g's ----------------
__global__ void act_quant(const float* __restrict__ x,
                          const float* g0, const float* g1, const float* g2,
                          signed char* xq0, signed char* xq1, signed char* xq2,
                          float* s0, float* s1, float* s2) {
    __shared__ float xr[DMODEL];
    __shared__ float red[256];
    int row = blockIdx.x, tid = threadIdx.x;
    const float* xp = x + (size_t)row*DMODEL;
    float ss = 0.f;
    #pragma unroll
    for (int l = 0; l < 8; l++) { float v = xp[tid + l*256]; xr[tid + l*256] = v; ss += v*v; }
    red[tid] = ss; __syncthreads();
    for (int st = 128; st > 0; st >>= 1) { if (tid < st) red[tid] += red[tid+st]; __syncthreads(); }
    float rinv = rsqrtf(red[0]*(1.f/(float)DMODEL) + 1e-6f);
    __syncthreads();

    const float* gs[3] = {g0, g1, g2};
    signed char* xqs[3] = {xq0, xq1, xq2};
    float* scs[3] = {s0, s1, s2};
    for (int vI = 0; vI < 3; vI++) {
        const float* g = gs[vI];
        if (!g) continue;
        float amax = 0.f, xn[8];
        #pragma unroll
        for (int l = 0; l < 8; l++) {
            int i = tid + l*256;
            float v = xr[i]*rinv*g[i];
            xn[l] = v; amax = fmaxf(amax, fabsf(v));
        }
        red[tid] = amax; __syncthreads();
        for (int st = 128; st > 0; st >>= 1) { if (tid < st) red[tid] = fmaxf(red[tid], red[tid+st]); __syncthreads(); }
        float sc = fmaxf(red[0], 1e-5f);
        __syncthreads();
        float qf = 127.f/sc;
        #pragma unroll
        for (int l = 0; l < 8; l++) {
            int i = tid + l*256;
            float q = rintf(xn[l]*qf);
            q = fminf(fmaxf(q, -128.f), 127.f);
            xqs[vI][(size_t)row*DMODEL + i] = (signed char)q;
        }
        if (tid == 0) scs[vI][row] = sc;
    }
}

// ---------------- int8 tensor-core GEMM via mma.sync.m16n8k32 ----------------
// C[M,N] = A[M,K=2048] * B[N,K]^T, A/B int8 row-major (K contiguous).
// CTA tile 128x128, 8 warps (2 m x 4 n), warp tile 64x32, K-chunk 128B, SW128 smem.
__global__ __launch_bounds__(256)
void gemm_imma(const signed char* __restrict__ A, const signed char* __restrict__ B,
               const float* __restrict__ xsc, int widx,
               float* __restrict__ C, int N) {
    __shared__ alignas(16) int4 As4[128*8];
    __shared__ alignas(16) int4 Bs4[128*8];
    const int K = 2048;
    int tid = threadIdx.x;
    int lane = tid & 31, warp = tid >> 5;
    int warp_m = warp >> 2, warp_n = warp & 3;     // 2 x 4
    int m0 = blockIdx.y*128, n0 = blockIdx.x*128;

    uint32_t asb = (uint32_t)__cvta_generic_to_shared(As4);
    uint32_t bsb = (uint32_t)__cvta_generic_to_shared(Bs4);

    int g = lane >> 3, lr = lane & 7;
    int rowA_base = warp_m*64 + (g&1)*8 + lr;
    int rowB_base = warp_n*32 + (g>>1)*8 + lr;
    int acolg = g >> 1, bcolg = g & 1;
    int grow = tid >> 3, gcol = tid & 7;

    int c[4][4][4];
    #pragma unroll
    for (int mt = 0; mt < 4; mt++)
        #pragma unroll
        for (int nt = 0; nt < 4; nt++)
            #pragma unroll
            for (int i = 0; i < 4; i++) c[mt][nt][i] = 0;

    for (int kb = 0; kb < K/128; kb++) {
        __syncthreads();
        #pragma unroll
        for (int l = 0; l < 4; l++) {
            int row = grow + l*32;
            const int4* ag = (const int4*)(A + (size_t)(m0 + row)*K + kb*128 + gcol*16);
            As4[row*8 + (gcol ^ (row & 7))] = *ag;
            const int4* bg = (const int4*)(B + (size_t)(n0 + row)*K + kb*128 + gcol*16);
            Bs4[row*8 + (gcol ^ (row & 7))] = *bg;
        }
        __syncthreads();
        #pragma unroll
        for (int kk = 0; kk < 4; kk++) {
            uint32_t a[4][4];
            #pragma unroll
            for (int mt = 0; mt < 4; mt++) {
                int rowA = rowA_base + mt*16;
                uint32_t addr = asb + (uint32_t)(rowA*128 + (((kk*2 + acolg) ^ lr) << 4));
                ldsm4(a[mt][0], a[mt][1], a[mt][2], a[mt][3], addr);
            }
            uint32_t bfr[4][2];
            #pragma unroll
            for (int nt2 = 0; nt2 < 2; nt2++) {
                int rowB = rowB_base + nt2*16;
                uint32_t addr = bsb + (uint32_t)(rowB*128 + (((kk*2 + bcolg) ^ lr) << 4));
                uint32_t r0, r1, r2, r3;
                ldsm4(r0, r1, r2, r3, addr);
                bfr[nt2*2][0] = r0;   bfr[nt2*2][1] = r1;
                bfr[nt2*2+1][0] = r2; bfr[nt2*2+1][1] = r3;
            }
            #pragma unroll
            for (int mt = 0; mt < 4; mt++)
                #pragma unroll
                for (int nt = 0; nt < 4; nt++)
                    imma16832(c[mt][nt], a[mt], bfr[nt]);
        }
    }

    float wsc = g_wscale[widx] * (1.f/127.f);
    int lane4 = lane >> 2, lanec = (lane & 3)*2;
    #pragma unroll
    for (int mt = 0; mt < 4; mt++) {
        int r0 = m0 + warp_m*64 + mt*16 + lane4;
        float s0 = wsc * xsc[r0];
        float s1 = wsc * xsc[r0 + 8];
        #pragma unroll
        for (int nt = 0; nt < 4; nt++) {
            int col = n0 + warp_n*32 + nt*8 + lanec;
            float2 v0, v1;
            v0.x = c[mt][nt][0]*s0; v0.y = c[mt][nt][1]*s0;
            v1.x = c[mt][nt][2]*s1; v1.y = c[mt][nt][3]*s1;
            *(float2*)&C[(size_t)r0*N + col] = v0;
            *(float2*)&C[(size_t)(r0+8)*N + col] = v1;
        }
    }
}

// ---------------- RoPE (in place), layout [token, h*64+d] ----------------
__global__ void rope_kernel(float* __restrict__ buf, const float* __restrict__ cs,
                            const float* __restrict__ sn, int nh) {
    int idx = blockIdx.x*blockDim.x + threadIdx.x;   // over NTOK*nh*32
    int i = idx & 31;
    int h = (idx >> 5) % nh;
    int tok = (idx >> 5) / nh;
    int t = tok & (SEQ - 1);
    float* p = buf + (size_t)tok*(nh*HD) + h*HD;
    float c0 = cs[t*HD + i],      s0 = sn[t*HD + i];
    float c1 = cs[t*HD + 32 + i], s1 = sn[t*HD + 32 + i];
    float a = p[i], b = p[32 + i];
    p[i]      = a*c0 - b*s0;
    p[32 + i] = b*c1 + a*s1;
}

// ---------------- causal flash attention, GQA (n_rep=4), 8x8 f32x2 register tile ----------------
// grid (SEQ/128, NH, B); 128 threads; dyn smem = 102400 B; 2 CTA/SM
__global__ __launch_bounds__(128, 2)
void attn_kernel(const float* __restrict__ Q, const float* __restrict__ K,
                 const float* __restrict__ V, float* __restrict__ O) {
    extern __shared__ float sm[];
    float* qT  = sm;                   // [64][132]  d-major: qT[d][i], i 0..127
    float* kT  = sm + 64*132;          // [64][68]   d-major: kT[d][j], j 0..63
    float* vs  = kT + 64*68;           // [64][68]   row-major: vs[j][d]
    float* psT = vs + 64*68;           // [64][132]  j-major: psT[j][i]
    int tid = threadIdx.x;
    int qt = blockIdx.x, h = blockIdx.y, b = blockIdx.z;
    int q0 = qt*128, kvh = h >> 2;
    int tx = tid & 7, ty = tid >> 3;   // tx: 8 j/d-groups of 8; ty: 16 row-groups of 8
    const float* Qb = Q + (size_t)(b*SEQ + q0)*DMODEL + h*HD;
    const float* Kb = K + (size_t)(b*SEQ)*(NKV*HD) + kvh*HD;
    const float* Vb = V + (size_t)(b*SEQ)*(NKV*HD) + kvh*HD;

    // load Q tile transposed (128 rows x 64 d -> qT[d][i])
    #pragma unroll
    for (int l = 0; l < 16; l++) {
        int idx = tid + l*128;            // 0..2047
        int r = idx >> 4, c4 = idx & 15;
        float4 f = *(const float4*)&Qb[(size_t)r*DMODEL + c4*4];
        qT[(c4*4+0)*132 + r] = f.x;
        qT[(c4*4+1)*132 + r] = f.y;
        qT[(c4*4+2)*132 + r] = f.z;
        qT[(c4*4+3)*132 + r] = f.w;
    }

    float m_i[8], l_i[8];
    unsigned long long o2[4][8];          // [row-pair][d], rows (2a, 2a+1), cols tx*8+d
    #pragma unroll
    for (int i = 0; i < 8; i++) { m_i[i] = -1e30f; l_i[i] = 0.f; }
    #pragma unroll
    for (int a = 0; a < 4; a++)
        #pragma unroll
        for (int d = 0; d < 8; d++) o2[a][d] = 0ull;

    int ktmax = 2*qt + 1;
    for (int kt = 0; kt <= ktmax; kt++) {
        int j0 = kt*64;
        __syncthreads();   // previous PV done before overwriting kT/vs
        // load K transposed + V straight (64 x 64 each)
        #pragma unroll
        for (int l = 0; l < 8; l++) {
            int idx = tid + l*128;        // 0..1023
            int r = idx >> 4, c4 = idx & 15;
            float4 f = *(const float4*)&Kb[(size_t)(j0 + r)*(NKV*HD) + c4*4];
            kT[(c4*4+0)*68 + r] = f.x;
            kT[(c4*4+1)*68 + r] = f.y;
            kT[(c4*4+2)*68 + r] = f.z;
            kT[(c4*4+3)*68 + r] = f.w;
            float4 g = *(const float4*)&Vb[(size_t)(j0 + r)*(NKV*HD) + c4*4];
            *(float4*)&vs[r*68 + c4*4] = g;
        }
        __syncthreads();

        // ---- S = Q @ K^T : s2[row-pair a][jj 0..7] over d ----
        unsigned long long s2[4][8];
        #pragma unroll
        for (int a = 0; a < 4; a++)
            #pragma unroll
            for (int j = 0; j < 8; j++) s2[a][j] = 0ull;

        #pragma unroll 2
        for (int d = 0; d < 64; d++) {
            ulonglong2 qa = *(const ulonglong2*)&qT[d*132 + ty*8];
            ulonglong2 qb2 = *(const ulonglong2*)&qT[d*132 + ty*8 + 4];
            float4 kf0 = *(const float4*)&kT[d*68 + tx*8];
            float4 kf1 = *(const float4*)&kT[d*68 + tx*8 + 4];
            unsigned long long kk[8];
            kk[0] = pack2(kf0.x, kf0.x); kk[1] = pack2(kf0.y, kf0.y);
            kk[2] = pack2(kf0.z, kf0.z); kk[3] = pack2(kf0.w, kf0.w);
            kk[4] = pack2(kf1.x, kf1.x); kk[5] = pack2(kf1.y, kf1.y);
            kk[6] = pack2(kf1.z, kf1.z); kk[7] = pack2(kf1.w, kf1.w);
            #pragma unroll
            for (int j = 0; j < 8; j++) {
                fma2(s2[0][j], qa.x, kk[j]);
                fma2(s2[1][j], qa.y, kk[j]);
                fma2(s2[2][j], qb2.x, kk[j]);
                fma2(s2[3][j], qb2.y, kk[j]);
            }
        }

        // ---- softmax (online) ----
        float sc[8][8];
        #pragma unroll
        for (int a = 0; a < 4; a++)
            #pragma unroll
            for (int j = 0; j < 8; j++)
                unpack2(s2[a][j], sc[2*a][j], sc[2*a+1][j]);

        bool needmask = (kt >= 2*qt);
        float corr[8];
        #pragma unroll
        for (int ii = 0; ii < 8; ii++) {
            int ig = q0 + ty*8 + ii;
            float tm = -1e30f;
            #pragma unroll
            for (int jj = 0; jj < 8; jj++) {
                float v = sc[ii][jj]*0.125f;
                if (needmask && (j0 + tx*8 + jj > ig)) v = -1e30f;
                sc[ii][jj] = v;
                tm = fmaxf(tm, v);
            }
            tm = fmaxf(tm, __shfl_xor_sync(0xffffffffu, tm, 1));
            tm = fmaxf(tm, __shfl_xor_sync(0xffffffffu, tm, 2));
            tm = fmaxf(tm, __shfl_xor_sync(0xffffffffu, tm, 4));
            float nm = fmaxf(m_i[ii], tm);
            corr[ii] = __expf(m_i[ii] - nm);
            m_i[ii] = nm;
            float ts = 0.f;
            #pragma unroll
            for (int jj = 0; jj < 8; jj++) {
                float p = __expf(sc[ii][jj] - nm);
                sc[ii][jj] = p; ts += p;
            }
            ts += __shfl_xor_sync(0xffffffffu, ts, 1);
            ts += __shfl_xor_sync(0xffffffffu, ts, 2);
            ts += __shfl_xor_sync(0xffffffffu, ts, 4);
            l_i[ii] = l_i[ii]*corr[ii] + ts;
        }
        // rescale O accumulators (packed row-pairs)
        #pragma unroll
        for (int a = 0; a < 4; a++) {
            unsigned long long c2 = pack2(corr[2*a], corr[2*a+1]);
            #pragma unroll
            for (int d = 0; d < 8; d++) o2[a][d] = mul2(o2[a][d], c2);
        }
        // store P transposed: psT[j][i]
        #pragma unroll
        for (int jj = 0; jj < 8; jj++) {
            float4 f0, f1;
            f0.x = sc[0][jj]; f0.y = sc[1][jj]; f0.z = sc[2][jj]; f0.w = sc[3][jj];
            f1.x = sc[4][jj]; f1.y = sc[5][jj]; f1.z = sc[6][jj]; f1.w = sc[7][jj];
            *(float4*)&psT[(tx*8+jj)*132 + ty*8] = f0;
            *(float4*)&psT[(tx*8+jj)*132 + ty*8 + 4] = f1;
        }
        __syncthreads();

        // ---- O += P @ V : reduce over j ----
        #pragma unroll 2
        for (int j = 0; j < 64; j++) {
            ulonglong2 pa = *(const ulonglong2*)&psT[j*132 + ty*8];
            ulonglong2 pb = *(const ulonglong2*)&psT[j*132 + ty*8 + 4];
            float4 vf0 = *(const float4*)&vs[j*68 + tx*8];
            float4 vf1 = *(const float4*)&vs[j*68 + tx*8 + 4];
            unsigned long long vv[8];
            vv[0] = pack2(vf0.x, vf0.x); vv[1] = pack2(vf0.y, vf0.y);
            vv[2] = pack2(vf0.z, vf0.z); vv[3] = pack2(vf0.w, vf0.w);
            vv[4] = pack2(vf1.x, vf1.x); vv[5] = pack2(vf1.y, vf1.y);
            vv[6] = pack2(vf1.z, vf1.z); vv[7] = pack2(vf1.w, vf1.w);
            #pragma unroll
            for (int d = 0; d < 8; d++) {
                fma2(o2[0][d], pa.x, vv[d]);
                fma2(o2[1][d], pa.y, vv[d]);
                fma2(o2[2][d], pb.x, vv[d]);
                fma2(o2[3][d], pb.y, vv[d]);
            }
        }
    }

    // ---- epilogue ----
    float* Ob = O + (size_t)(b*SEQ + q0)*DMODEL + h*HD;
    #pragma unroll
    for (int a = 0; a < 4; a++) {
        float lo[8], hi[8];
        #pragma unroll
        for (int d = 0; d < 8; d++) unpack2(o2[a][d], lo[d], hi[d]);
        float inv0 = 1.f / l_i[2*a];
        float inv1 = 1.f / l_i[2*a+1];
        float4 f0a, f0b, f1a, f1b;
        f0a.x = lo[0]*inv0; f0a.y = lo[1]*inv0; f0a.z = lo[2]*inv0; f0a.w = lo[3]*inv0;
        f0b.x = lo[4]*inv0; f0b.y = lo[5]*inv0; f0b.z = lo[6]*inv0; f0b.w = lo[7]*inv0;
        f1a.x = hi[0]*inv1; f1a.y = hi[1]*inv1; f1a.z = hi[2]*inv1; f1a.w = hi[3]*inv1;
        f1b.x = hi[4]*inv1; f1b.y = hi[5]*inv1; f1b.z = hi[6]*inv1; f1b.w = hi[7]*inv1;
        *(float4*)&Ob[(size_t)(ty*8 + 2*a    )*DMODEL + tx*8] = f0a;
        *(float4*)&Ob[(size_t)(ty*8 + 2*a    )*DMODEL + tx*8 + 4] = f0b;
        *(float4*)&Ob[(size_t)(ty*8 + 2*a + 1)*DMODEL + tx*8] = f1a;
        *(float4*)&Ob[(size_t)(ty*8 + 2*a + 1)*DMODEL + tx*8 + 4] = f1b;
    }
}

// ---------------- launch ----------------
extern "C" void kernel_launch(void* const* d_in, const int* in_sizes, int n_in,
                              void* d_out, int out_size) {
    const float* x   = (const float*)d_in[0];
    const float* cs  = (const float*)d_in[1];
    const float* sn  = (const float*)d_in[2];
    const float* wq  = (const float*)d_in[3];
    const float* wk  = (const float*)d_in[4];
    const float* wv  = (const float*)d_in[5];
    const float* wo  = (const float*)d_in[6];
    const float* gq  = (const float*)d_in[7];
    const float* gk  = (const float*)d_in[8];
    const float* gv  = (const float*)d_in[9];
    const float* go  = (const float*)d_in[10];
    float* out = (float*)d_out;

    signed char *wq_q, *wk_q, *wv_q, *wo_q, *xq0, *xq1, *xq2, *xqo;
    float *xs0, *xs1, *xs2, *xso, *projq, *projk, *projv, *attnb;
    cudaGetSymbolAddress((void**)&wq_q, g_wq);
    cudaGetSymbolAddress((void**)&wk_q, g_wk);
    cudaGetSymbolAddress((void**)&wv_q, g_wv);
    cudaGetSymbolAddress((void**)&wo_q, g_wo);
    cudaGetSymbolAddress((void**)&xq0, g_xq0);
    cudaGetSymbolAddress((void**)&xq1, g_xq1);
    cudaGetSymbolAddress((void**)&xq2, g_xq2);
    cudaGetSymbolAddress((void**)&xqo, g_xqo);
    cudaGetSymbolAddress((void**)&xs0, g_xs0);
    cudaGetSymbolAddress((void**)&xs1, g_xs1);
    cudaGetSymbolAddress((void**)&xs2, g_xs2);
    cudaGetSymbolAddress((void**)&xso, g_xso);
    cudaGetSymbolAddress((void**)&projq, g_projq);
    cudaGetSymbolAddress((void**)&projk, g_projk);
    cudaGetSymbolAddress((void**)&projv, g_projv);
    cudaGetSymbolAddress((void**)&attnb, g_attn);

    cudaFuncSetAttribute(attn_kernel, cudaFuncAttributeMaxDynamicSharedMemorySize, 102400);

    // weight scales + ternary quant
    absum_partial<<<256, 256>>>(wq, DMODEL*DMODEL, 0);
    absum_partial<<<256, 256>>>(wk, NKV*HD*DMODEL, 1);
    absum_partial<<<256, 256>>>(wv, NKV*HD*DMODEL, 2);
    absum_partial<<<256, 256>>>(wo, DMODEL*DMODEL, 3);
    finalize_wscale<<<1, 256>>>();
    quant_w<<<2048, 256>>>(wq, wq_q, DMODEL*DMODEL, 0);
    quant_w<<<512, 256>>>(wk, wk_q, NKV*HD*DMODEL, 1);
    quant_w<<<512, 256>>>(wv, wv_q, NKV*HD*DMODEL, 2);
    quant_w<<<2048, 256>>>(wo, wo_q, DMODEL*DMODEL, 3);

    // activation quant (3 projections share x row + rmsnorm stat)
    act_quant<<<NTOK, 256>>>(x, gq, gk, gv, xq0, xq1, xq2, xs0, xs1, xs2);

    // projections (tensor-core int8)
    gemm_imma<<<dim3(DMODEL/128, NTOK/128), 256>>>(xq0, wq_q, xs0, 0, projq, DMODEL);
    gemm_imma<<<dim3((NKV*HD)/128, NTOK/128), 256>>>(xq1, wk_q, xs1, 1, projk, NKV*HD);
    gemm_imma<<<dim3((NKV*HD)/128, NTOK/128), 256>>>(xq2, wv_q, xs2, 2, projv, NKV*HD);

    // rope
    rope_kernel<<<(NTOK*NH*32)/256, 256>>>(projq, cs, sn, NH);
    rope_kernel<<<(NTOK*NKV*32)/256, 256>>>(projk, cs, sn, NKV);

    // attention
    attn_kernel<<<dim3(SEQ/128, NH, BATCH), 128, 102400>>>(projq, projk, projv, attnb);

    // output bitlinear
    act_quant<<<NTOK, 256>>>(attnb, go, nullptr, nullptr, xqo, nullptr, nullptr, xso, nullptr, nullptr);
    gemm_imma<<<dim3(DMODEL/128, NTOK/128), 256>>>(xqo, wo_q, xso, 3, out, DMODEL);
}

// round 6
// speedup vs baseline: 1.0948x; 1.0948x over previous
#include <cuda_runtime.h>
#include <cuda_bf16.h>
#include <cstdint>

// Problem constants (fixed shapes)
#define BATCH 2
#define SEQ   2048
#define DMODEL 2048
#define NH    32
#define NKV   8
#define HD    64
#define NTOK  (BATCH*SEQ)          // 4096

// ---------------- f32x2 packed math helpers ----------------
__device__ __forceinline__ void fma2(unsigned long long &d, unsigned long long a, unsigned long long b) {
    asm("fma.rn.f32x2 %0, %1, %2, %0;" : "+l"(d) : "l"(a), "l"(b));
}
__device__ __forceinline__ unsigned long long mul2(unsigned long long a, unsigned long long b) {
    unsigned long long r;
    asm("mul.rn.f32x2 %0, %1, %2;" : "=l"(r) : "l"(a), "l"(b));
    return r;
}
__device__ __forceinline__ unsigned long long pack2(float lo, float hi) {
    unsigned long long r;
    asm("mov.b64 %0, {%1, %2};" : "=l"(r) : "f"(lo), "f"(hi));
    return r;
}
__device__ __forceinline__ void unpack2(unsigned long long v, float &lo, float &hi) {
    asm("mov.b64 {%0, %1}, %2;" : "=f"(lo), "=f"(hi) : "l"(v));
}
__device__ __forceinline__ float ex2(float x) {
    float r;
    asm("ex2.approx.ftz.f32 %0, %1;" : "=f"(r) : "f"(x));
    return r;
}

// ---------------- mma.sync / ldmatrix helpers ----------------
__device__ __forceinline__ void ldsm4(uint32_t &r0, uint32_t &r1, uint32_t &r2, uint32_t &r3, uint32_t addr) {
    asm volatile("ldmatrix.sync.aligned.m8n8.x4.shared.b16 {%0,%1,%2,%3}, [%4];"
                 : "=r"(r0), "=r"(r1), "=r"(r2), "=r"(r3) : "r"(addr));
}
__device__ __forceinline__ void imma16832(int* c, const uint32_t* a, const uint32_t* b) {
    asm volatile("mma.sync.aligned.m16n8k32.row.col.s32.s8.s8.s32 "
                 "{%0,%1,%2,%3}, {%4,%5,%6,%7}, {%8,%9}, {%0,%1,%2,%3};"
                 : "+r"(c[0]), "+r"(c[1]), "+r"(c[2]), "+r"(c[3])
                 : "r"(a[0]), "r"(a[1]), "r"(a[2]), "r"(a[3]), "r"(b[0]), "r"(b[1]));
}

// ---------------- device scratch (static, allocation-free) ----------------
__device__ float g_partial[4*256];
__device__ float g_wscale[4];
__device__ __align__(16) signed char g_wq[DMODEL*DMODEL];
__device__ __align__(16) signed char g_wk[NKV*HD*DMODEL];
__device__ __align__(16) signed char g_wv[NKV*HD*DMODEL];
__device__ __align__(16) signed char g_wo[DMODEL*DMODEL];
__device__ __align__(16) signed char g_xq0[NTOK*DMODEL];
__device__ __align__(16) signed char g_xq1[NTOK*DMODEL];
__device__ __align__(16) signed char g_xq2[NTOK*DMODEL];
__device__ __align__(16) signed char g_xqo[NTOK*DMODEL];
__device__ float g_xs0[NTOK];
__device__ float g_xs1[NTOK];
__device__ float g_xs2[NTOK];
__device__ float g_xso[NTOK];
__device__ float g_projq[NTOK*DMODEL];     // [token, h*64+d]
__device__ float g_projk[NTOK*NKV*HD];     // [token, kv*64+d]
__device__ float g_projv[NTOK*NKV*HD];
__device__ float g_attn[NTOK*DMODEL];      // [token, h*64+d]

// ---------------- weight abs-mean: 4 matrices in one launch ----------------
__global__ void absum_all(const float* __restrict__ w0, const float* __restrict__ w1,
                          const float* __restrict__ w2, const float* __restrict__ w3) {
    __shared__ float red[256];
    const float* ws[4] = {w0, w1, w2, w3};
    const int    ns[4] = {DMODEL*DMODEL, NKV*HD*DMODEL, NKV*HD*DMODEL, DMODEL*DMODEL};
    int k = blockIdx.y;
    const float* w = ws[k];
    int n = ns[k];
    int tid = threadIdx.x;
    float s = 0.f;
    for (int i = blockIdx.x*256 + tid; i < n; i += 256*256) s += fabsf(w[i]);
    red[tid] = s; __syncthreads();
    for (int st = 128; st > 0; st >>= 1) { if (tid < st) red[tid] += red[tid+st]; __syncthreads(); }
    if (tid == 0) g_partial[k*256 + blockIdx.x] = red[0];
}

__global__ void finalize_wscale() {
    __shared__ float red[256];
    int tid = threadIdx.x;
    const float ninv[4] = {1.f/(2048.f*2048.f), 1.f/(512.f*2048.f),
                           1.f/(512.f*2048.f), 1.f/(2048.f*2048.f)};
    for (int k = 0; k < 4; k++) {
        red[tid] = g_partial[k*256 + tid]; __syncthreads();
        for (int st = 128; st > 0; st >>= 1) { if (tid < st) red[tid] += red[tid+st]; __syncthreads(); }
        if (tid == 0) g_wscale[k] = fmaxf(red[0]*ninv[k], 1e-5f);
        __syncthreads();
    }
}

// ---------------- ternary weight quant: 4 matrices in one launch ----------------
__global__ void quant_all(const float* __restrict__ w0, const float* __restrict__ w1,
                          const float* __restrict__ w2, const float* __restrict__ w3,
                          signed char* o0, signed char* o1, signed char* o2v, signed char* o3) {
    const float* ws[4] = {w0, w1, w2, w3};
    signed char* os[4] = {o0, o1, o2v, o3};
    const int    ns[4] = {DMODEL*DMODEL, NKV*HD*DMODEL, NKV*HD*DMODEL, DMODEL*DMODEL};
    int k = blockIdx.y;
    const float* w = ws[k];
    signed char* o = os[k];
    int n = ns[k];
    float inv = 1.f / g_wscale[k];
    for (int i = blockIdx.x*blockDim.x + threadIdx.x; i < n; i += gridDim.x*blockDim.x) {
        float q = rintf(w[i]*inv);
        q = fminf(fmaxf(q, -1.f), 1.f);
        o[i] = (signed char)q;
    }
}

// ---------------- activation quant (rmsnorm + absmax int8), up to 3 g's ----------------
__global__ void act_quant(const float* __restrict__ x,
                          const float* g0, const float* g1, const float* g2,
                          signed char* xq0, signed char* xq1, signed char* xq2,
                          float* s0, float* s1, float* s2) {
    __shared__ float xr[DMODEL];
    __shared__ float red[256];
    int row = blockIdx.x, tid = threadIdx.x;
    const float* xp = x + (size_t)row*DMODEL;
    float ss = 0.f;
    #pragma unroll
    for (int l = 0; l < 8; l++) { float v = xp[tid + l*256]; xr[tid + l*256] = v; ss += v*v; }
    red[tid] = ss; __syncthreads();
    for (int st = 128; st > 0; st >>= 1) { if (tid < st) red[tid] += red[tid+st]; __syncthreads(); }
    float rinv = rsqrtf(red[0]*(1.f/(float)DMODEL) + 1e-6f);
    __syncthreads();

    const float* gs[3] = {g0, g1, g2};
    signed char* xqs[3] = {xq0, xq1, xq2};
    float* scs[3] = {s0, s1, s2};
    for (int vI = 0; vI < 3; vI++) {
        const float* g = gs[vI];
        if (!g) continue;
        float amax = 0.f, xn[8];
        #pragma unroll
        for (int l = 0; l < 8; l++) {
            int i = tid + l*256;
            float v = xr[i]*rinv*g[i];
            xn[l] = v; amax = fmaxf(amax, fabsf(v));
        }
        red[tid] = amax; __syncthreads();
        for (int st = 128; st > 0; st >>= 1) { if (tid < st) red[tid] = fmaxf(red[tid], red[tid+st]); __syncthreads(); }
        float sc = fmaxf(red[0], 1e-5f);
        __syncthreads();
        float qf = 127.f/sc;
        #pragma unroll
        for (int l = 0; l < 8; l++) {
            int i = tid + l*256;
            float q = rintf(xn[l]*qf);
            q = fminf(fmaxf(q, -128.f), 127.f);
            xqs[vI][(size_t)row*DMODEL + i] = (signed char)q;
        }
        if (tid == 0) scs[vI][row] = sc;
    }
}

// ---------------- int8 tensor-core GEMM via mma.sync.m16n8k32 ----------------
__global__ __launch_bounds__(256)
void gemm_imma(const signed char* __restrict__ A, const signed char* __restrict__ B,
               const float* __restrict__ xsc, int widx,
               float* __restrict__ C, int N) {
    __shared__ alignas(16) int4 As4[128*8];
    __shared__ alignas(16) int4 Bs4[128*8];
    const int K = 2048;
    int tid = threadIdx.x;
    int lane = tid & 31, warp = tid >> 5;
    int warp_m = warp >> 2, warp_n = warp & 3;     // 2 x 4
    int m0 = blockIdx.y*128, n0 = blockIdx.x*128;

    uint32_t asb = (uint32_t)__cvta_generic_to_shared(As4);
    uint32_t bsb = (uint32_t)__cvta_generic_to_shared(Bs4);

    int g = lane >> 3, lr = lane & 7;
    int rowA_base = warp_m*64 + (g&1)*8 + lr;
    int rowB_base = warp_n*32 + (g>>1)*8 + lr;
    int acolg = g >> 1, bcolg = g & 1;
    int grow = tid >> 3, gcol = tid & 7;

    int c[4][4][4];
    #pragma unroll
    for (int mt = 0; mt < 4; mt++)
        #pragma unroll
        for (int nt = 0; nt < 4; nt++)
            #pragma unroll
            for (int i = 0; i < 4; i++) c[mt][nt][i] = 0;

    for (int kb = 0; kb < K/128; kb++) {
        __syncthreads();
        #pragma unroll
        for (int l = 0; l < 4; l++) {
            int row = grow + l*32;
            const int4* ag = (const int4*)(A + (size_t)(m0 + row)*K + kb*128 + gcol*16);
            As4[row*8 + (gcol ^ (row & 7))] = *ag;
            const int4* bg = (const int4*)(B + (size_t)(n0 + row)*K + kb*128 + gcol*16);
            Bs4[row*8 + (gcol ^ (row & 7))] = *bg;
        }
        __syncthreads();
        #pragma unroll
        for (int kk = 0; kk < 4; kk++) {
            uint32_t a[4][4];
            #pragma unroll
            for (int mt = 0; mt < 4; mt++) {
                int rowA = rowA_base + mt*16;
                uint32_t addr = asb + (uint32_t)(rowA*128 + (((kk*2 + acolg) ^ lr) << 4));
                ldsm4(a[mt][0], a[mt][1], a[mt][2], a[mt][3], addr);
            }
            uint32_t bfr[4][2];
            #pragma unroll
            for (int nt2 = 0; nt2 < 2; nt2++) {
                int rowB = rowB_base + nt2*16;
                uint32_t addr = bsb + (uint32_t)(rowB*128 + (((kk*2 + bcolg) ^ lr) << 4));
                uint32_t r0, r1, r2, r3;
                ldsm4(r0, r1, r2, r3, addr);
                bfr[nt2*2][0] = r0;   bfr[nt2*2][1] = r1;
                bfr[nt2*2+1][0] = r2; bfr[nt2*2+1][1] = r3;
            }
            #pragma unroll
            for (int mt = 0; mt < 4; mt++)
                #pragma unroll
                for (int nt = 0; nt < 4; nt++)
                    imma16832(c[mt][nt], a[mt], bfr[nt]);
        }
    }

    float wsc = g_wscale[widx] * (1.f/127.f);
    int lane4 = lane >> 2, lanec = (lane & 3)*2;
    #pragma unroll
    for (int mt = 0; mt < 4; mt++) {
        int r0 = m0 + warp_m*64 + mt*16 + lane4;
        float s0 = wsc * xsc[r0];
        float s1 = wsc * xsc[r0 + 8];
        #pragma unroll
        for (int nt = 0; nt < 4; nt++) {
            int col = n0 + warp_n*32 + nt*8 + lanec;
            float2 v0, v1;
            v0.x = c[mt][nt][0]*s0; v0.y = c[mt][nt][1]*s0;
            v1.x = c[mt][nt][2]*s1; v1.y = c[mt][nt][3]*s1;
            *(float2*)&C[(size_t)r0*N + col] = v0;
            *(float2*)&C[(size_t)(r0+8)*N + col] = v1;
        }
    }
}

// ---------------- RoPE (in place), q + k in one launch ----------------
__global__ void rope_all(float* __restrict__ bq, float* __restrict__ bk,
                         const float* __restrict__ cs, const float* __restrict__ sn) {
    int idx = blockIdx.x*blockDim.x + threadIdx.x;
    const int qtot = NTOK*NH*32;
    float* buf; int nh;
    if (idx < qtot) { buf = bq; nh = NH; }
    else            { buf = bk; nh = NKV; idx -= qtot; }
    int i = idx & 31;
    int h = (idx >> 5) % nh;
    int tok = (idx >> 5) / nh;
    int t = tok & (SEQ - 1);
    float* p = buf + (size_t)tok*(nh*HD) + h*HD;
    float c0 = cs[t*HD + i],      s0 = sn[t*HD + i];
    float c1 = cs[t*HD + 32 + i], s1 = sn[t*HD + 32 + i];
    float a = p[i], b = p[32 + i];
    p[i]      = a*c0 - b*s0;
    p[32 + i] = b*c1 + a*s1;
}

// ---------------- causal flash attention, GQA (n_rep=4), f32x2 register-tiled ----------------
// grid (SEQ/128, NH, B); 256 threads; dyn smem = 102400 B; 2 CTA/SM
// Q pre-scaled by 0.125*log2(e); softmax runs in exp2 domain.
#define QSC (0.125f * 1.4426950408889634f)
__global__ __launch_bounds__(256, 2)
void attn_kernel(const float* __restrict__ Q, const float* __restrict__ K,
                 const float* __restrict__ V, float* __restrict__ O) {
    extern __shared__ float sm[];
    float* qT  = sm;                   // [64][132]  d-major: qT[d][i], i 0..127
    float* kT  = sm + 64*132;          // [64][68]   d-major: kT[d][j], j 0..63
    float* vs  = kT + 64*68;           // [64][68]   row-major: vs[j][d]
    float* psT = vs + 64*68;           // [64][132]  j-major: psT[j][i]
    int tid = threadIdx.x;
    int qt = blockIdx.x, h = blockIdx.y, b = blockIdx.z;
    int q0 = qt*128, kvh = h >> 2;
    int tx = tid & 15, ty = tid >> 4;
    const float* Qb = Q + (size_t)(b*SEQ + q0)*DMODEL + h*HD;
    const float* Kb = K + (size_t)(b*SEQ)*(NKV*HD) + kvh*HD;
    const float* Vb = V + (size_t)(b*SEQ)*(NKV*HD) + kvh*HD;

    // load Q tile transposed (128 rows x 64 d -> qT[d][i]), pre-scaled
    #pragma unroll
    for (int l = 0; l < 8; l++) {
        int idx = tid + l*256;            // 0..2047
        int r = idx >> 4, c4 = idx & 15;
        float4 f = *(const float4*)&Qb[(size_t)r*DMODEL + c4*4];
        qT[(c4*4+0)*132 + r] = f.x*QSC;
        qT[(c4*4+1)*132 + r] = f.y*QSC;
        qT[(c4*4+2)*132 + r] = f.z*QSC;
        qT[(c4*4+3)*132 + r] = f.w*QSC;
    }

    float m_i[8], l_i[8];
    unsigned long long o2[4][4];          // [row-pair][dd], rows (ty*8+2a, ty*8+2a+1)
    #pragma unroll
    for (int i = 0; i < 8; i++) { m_i[i] = -1e30f; l_i[i] = 0.f; }
    #pragma unroll
    for (int a = 0; a < 4; a++)
        #pragma unroll
        for (int d = 0; d < 4; d++) o2[a][d] = 0ull;

    int ktmax = 2*qt + 1;
    for (int kt = 0; kt <= ktmax; kt++) {
        int j0 = kt*64;
        __syncthreads();   // previous PV done before overwriting kT/vs
        // load K transposed + V straight (64 x 64 each)
        #pragma unroll
        for (int l = 0; l < 4; l++) {
            int idx = tid + l*256;        // 0..1023
            int r = idx >> 4, c4 = idx & 15;
            float4 f = *(const float4*)&Kb[(size_t)(j0 + r)*(NKV*HD) + c4*4];
            kT[(c4*4+0)*68 + r] = f.x;
            kT[(c4*4+1)*68 + r] = f.y;
            kT[(c4*4+2)*68 + r] = f.z;
            kT[(c4*4+3)*68 + r] = f.w;
            float4 g = *(const float4*)&Vb[(size_t)(j0 + r)*(NKV*HD) + c4*4];
            *(float4*)&vs[r*68 + c4*4] = g;
        }
        __syncthreads();

        // ---- S = Q @ K^T : s2[row-pair a][jj] over d (already log2e-scaled) ----
        unsigned long long s2[4][4];
        #pragma unroll
        for (int a = 0; a < 4; a++)
            #pragma unroll
            for (int j = 0; j < 4; j++) s2[a][j] = 0ull;

        #pragma unroll 4
        for (int d = 0; d < 64; d++) {
            ulonglong2 qa = *(const ulonglong2*)&qT[d*132 + ty*8];
            ulonglong2 qb2 = *(const ulonglong2*)&qT[d*132 + ty*8 + 4];
            float4 kf = *(const float4*)&kT[d*68 + tx*4];
            unsigned long long k0 = pack2(kf.x, kf.x);
            unsigned long long k1 = pack2(kf.y, kf.y);
            unsigned long long k2 = pack2(kf.z, kf.z);
            unsigned long long k3 = pack2(kf.w, kf.w);
            fma2(s2[0][0], qa.x, k0);  fma2(s2[0][1], qa.x, k1);
            fma2(s2[0][2], qa.x, k2);  fma2(s2[0][3], qa.x, k3);
            fma2(s2[1][0], qa.y, k0);  fma2(s2[1][1], qa.y, k1);
            fma2(s2[1][2], qa.y, k2);  fma2(s2[1][3], qa.y, k3);
            fma2(s2[2][0], qb2.x, k0); fma2(s2[2][1], qb2.x, k1);
            fma2(s2[2][2], qb2.x, k2); fma2(s2[2][3], qb2.x, k3);
            fma2(s2[3][0], qb2.y, k0); fma2(s2[3][1], qb2.y, k1);
            fma2(s2[3][2], qb2.y, k2); fma2(s2[3][3], qb2.y, k3);
        }

        // ---- softmax (online, exp2 domain) ----
        float sc[8][4];
        #pragma unroll
        for (int a = 0; a < 4; a++)
            #pragma unroll
            for (int j = 0; j < 4; j++)
                unpack2(s2[a][j], sc[2*a][j], sc[2*a+1][j]);

        bool needmask = (kt >= 2*qt);
        float corr[8];
        #pragma unroll
        for (int ii = 0; ii < 8; ii++) {
            int ig = q0 + ty*8 + ii;
            float tm = -1e30f;
            #pragma unroll
            for (int jj = 0; jj < 4; jj++) {
                float v = sc[ii][jj];
                if (needmask && (j0 + tx*4 + jj > ig)) v = -1e30f;
                sc[ii][jj] = v;
                tm = fmaxf(tm, v);
            }
            tm = fmaxf(tm, __shfl_xor_sync(0xffffffffu, tm, 1));
            tm = fmaxf(tm, __shfl_xor_sync(0xffffffffu, tm, 2));
            tm = fmaxf(tm, __shfl_xor_sync(0xffffffffu, tm, 4));
            tm = fmaxf(tm, __shfl_xor_sync(0xffffffffu, tm, 8));
            float nm = fmaxf(m_i[ii], tm);
            corr[ii] = ex2(m_i[ii] - nm);
            m_i[ii] = nm;
            float ts = 0.f;
            #pragma unroll
            for (int jj = 0; jj < 4; jj++) {
                float p = ex2(sc[ii][jj] - nm);
                sc[ii][jj] = p; ts += p;
            }
            ts += __shfl_xor_sync(0xffffffffu, ts, 1);
            ts += __shfl_xor_sync(0xffffffffu, ts, 2);
            ts += __shfl_xor_sync(0xffffffffu, ts, 4);
            ts += __shfl_xor_sync(0xffffffffu, ts, 8);
            l_i[ii] = l_i[ii]*corr[ii] + ts;
        }
        // rescale O accumulators (packed row-pairs)
        #pragma unroll
        for (int a = 0; a < 4; a++) {
            unsigned long long c2 = pack2(corr[2*a], corr[2*a+1]);
            #pragma unroll
            for (int d = 0; d < 4; d++) o2[a][d] = mul2(o2[a][d], c2);
        }
        // store P transposed: psT[j][i]
        #pragma unroll
        for (int jj = 0; jj < 4; jj++)
            #pragma unroll
            for (int ii = 0; ii < 8; ii++)
                psT[(tx*4+jj)*132 + ty*8 + ii] = sc[ii][jj];
        __syncthreads();

        // ---- O += P @ V : reduce over j ----
        #pragma unroll 4
        for (int j = 0; j < 64; j++) {
            ulonglong2 pa = *(const ulonglong2*)&psT[j*132 + ty*8];
            ulonglong2 pb = *(const ulonglong2*)&psT[j*132 + ty*8 + 4];
            float4 vf = *(const float4*)&vs[j*68 + tx*4];
            unsigned long long v0 = pack2(vf.x, vf.x);
            unsigned long long v1 = pack2(vf.y, vf.y);
            unsigned long long v2 = pack2(vf.z, vf.z);
            unsigned long long v3 = pack2(vf.w, vf.w);
            fma2(o2[0][0], pa.x, v0);  fma2(o2[0][1], pa.x, v1);
            fma2(o2[0][2], pa.x, v2);  fma2(o2[0][3], pa.x, v3);
            fma2(o2[1][0], pa.y, v0);  fma2(o2[1][1], pa.y, v1);
            fma2(o2[1][2], pa.y, v2);  fma2(o2[1][3], pa.y, v3);
            fma2(o2[2][0], pb.x, v0);  fma2(o2[2][1], pb.x, v1);
            fma2(o2[2][2], pb.x, v2);  fma2(o2[2][3], pb.x, v3);
            fma2(o2[3][0], pb.y, v0);  fma2(o2[3][1], pb.y, v1);
            fma2(o2[3][2], pb.y, v2);  fma2(o2[3][3], pb.y, v3);
        }
    }

    // ---- epilogue ----
    float* Ob = O + (size_t)(b*SEQ + q0)*DMODEL + h*HD;
    #pragma unroll
    for (int a = 0; a < 4; a++) {
        float lo[4], hi[4];
        #pragma unroll
        for (int d = 0; d < 4; d++) unpack2(o2[a][d], lo[d], hi[d]);
        float inv0 = 1.f / l_i[2*a];
        float inv1 = 1.f / l_i[2*a+1];
        float4 f0, f1;
        f0.x = lo[0]*inv0; f0.y = lo[1]*inv0; f0.z = lo[2]*inv0; f0.w = lo[3]*inv0;
        f1.x = hi[0]*inv1; f1.y = hi[1]*inv1; f1.z = hi[2]*inv1; f1.w = hi[3]*inv1;
        *(float4*)&Ob[(size_t)(ty*8 + 2*a    )*DMODEL + tx*4] = f0;
        *(float4*)&Ob[(size_t)(ty*8 + 2*a + 1)*DMODEL + tx*4] = f1;
    }
}

// ---------------- launch ----------------
extern "C" void kernel_launch(void* const* d_in, const int* in_sizes, int n_in,
                              void* d_out, int out_size) {
    const float* x   = (const float*)d_in[0];
    const float* cs  = (const float*)d_in[1];
    const float* sn  = (const float*)d_in[2];
    const float* wq  = (const float*)d_in[3];
    const float* wk  = (const float*)d_in[4];
    const float* wv  = (const float*)d_in[5];
    const float* wo  = (const float*)d_in[6];
    const float* gq  = (const float*)d_in[7];
    const float* gk  = (const float*)d_in[8];
    const float* gv  = (const float*)d_in[9];
    const float* go  = (const float*)d_in[10];
    float* out = (float*)d_out;

    signed char *wq_q, *wk_q, *wv_q, *wo_q, *xq0, *xq1, *xq2, *xqo;
    float *xs0, *xs1, *xs2, *xso, *projq, *projk, *projv, *attnb;
    cudaGetSymbolAddress((void**)&wq_q, g_wq);
    cudaGetSymbolAddress((void**)&wk_q, g_wk);
    cudaGetSymbolAddress((void**)&wv_q, g_wv);
    cudaGetSymbolAddress((void**)&wo_q, g_wo);
    cudaGetSymbolAddress((void**)&xq0, g_xq0);
    cudaGetSymbolAddress((void**)&xq1, g_xq1);
    cudaGetSymbolAddress((void**)&xq2, g_xq2);
    cudaGetSymbolAddress((void**)&xqo, g_xqo);
    cudaGetSymbolAddress((void**)&xs0, g_xs0);
    cudaGetSymbolAddress((void**)&xs1, g_xs1);
    cudaGetSymbolAddress((void**)&xs2, g_xs2);
    cudaGetSymbolAddress((void**)&xso, g_xso);
    cudaGetSymbolAddress((void**)&projq, g_projq);
    cudaGetSymbolAddress((void**)&projk, g_projk);
    cudaGetSymbolAddress((void**)&projv, g_projv);
    cudaGetSymbolAddress((void**)&attnb, g_attn);

    cudaFuncSetAttribute(attn_kernel, cudaFuncAttributeMaxDynamicSharedMemorySize, 102400);

    // weight scales + ternary quant (fused launches)
    absum_all<<<dim3(256, 4), 256>>>(wq, wk, wv, wo);
    finalize_wscale<<<1, 256>>>();
    quant_all<<<dim3(1024, 4), 256>>>(wq, wk, wv, wo, wq_q, wk_q, wv_q, wo_q);

    // activation quant (3 projections share x row + rmsnorm stat)
    act_quant<<<NTOK, 256>>>(x, gq, gk, gv, xq0, xq1, xq2, xs0, xs1, xs2);

    // projections (tensor-core int8)
    gemm_imma<<<dim3(DMODEL/128, NTOK/128), 256>>>(xq0, wq_q, xs0, 0, projq, DMODEL);
    gemm_imma<<<dim3((NKV*HD)/128, NTOK/128), 256>>>(xq1, wk_q, xs1, 1, projk, NKV*HD);
    gemm_imma<<<dim3((NKV*HD)/128, NTOK/128), 256>>>(xq2, wv_q, xs2, 2, projv, NKV*HD);

    // rope (q + k fused)
    rope_all<<<(NTOK*(NH+NKV)*32)/256, 256>>>(projq, projk, cs, sn);

    // attention
    attn_kernel<<<dim3(SEQ/128, NH, BATCH), 256, 102400>>>(projq, projk, projv, attnb);

    // output bitlinear
    act_quant<<<NTOK, 256>>>(attnb, go, nullptr, nullptr, xqo, nullptr, nullptr, xso, nullptr, nullptr);
    gemm_imma<<<dim3(DMODEL/128, NTOK/128), 256>>>(xqo, wo_q, xso, 3, out, DMODEL);
}

// round 7
// speedup vs baseline: 1.0968x; 1.0018x over previous
#include <cuda_runtime.h>
#include <cuda_bf16.h>
#include <cstdint>

// Problem constants (fixed shapes)
#define BATCH 2
#define SEQ   2048
#define DMODEL 2048
#define NH    32
#define NKV   8
#define HD    64
#define NTOK  (BATCH*SEQ)          // 4096

// ---------------- f32x2 packed math helpers ----------------
__device__ __forceinline__ void fma2(unsigned long long &d, unsigned long long a, unsigned long long b) {
    asm("fma.rn.f32x2 %0, %1, %2, %0;" : "+l"(d) : "l"(a), "l"(b));
}
__device__ __forceinline__ unsigned long long mul2(unsigned long long a, unsigned long long b) {
    unsigned long long r;
    asm("mul.rn.f32x2 %0, %1, %2;" : "=l"(r) : "l"(a), "l"(b));
    return r;
}
__device__ __forceinline__ unsigned long long pack2(float lo, float hi) {
    unsigned long long r;
    asm("mov.b64 %0, {%1, %2};" : "=l"(r) : "f"(lo), "f"(hi));
    return r;
}
__device__ __forceinline__ void unpack2(unsigned long long v, float &lo, float &hi) {
    asm("mov.b64 {%0, %1}, %2;" : "=f"(lo), "=f"(hi) : "l"(v));
}
__device__ __forceinline__ float ex2(float x) {
    float r;
    asm("ex2.approx.ftz.f32 %0, %1;" : "=f"(r) : "f"(x));
    return r;
}

// ---------------- mma.sync / ldmatrix helpers ----------------
__device__ __forceinline__ void ldsm4(uint32_t &r0, uint32_t &r1, uint32_t &r2, uint32_t &r3, uint32_t addr) {
    asm volatile("ldmatrix.sync.aligned.m8n8.x4.shared.b16 {%0,%1,%2,%3}, [%4];"
                 : "=r"(r0), "=r"(r1), "=r"(r2), "=r"(r3) : "r"(addr));
}
__device__ __forceinline__ void imma16832(int* c, const uint32_t* a, const uint32_t* b) {
    asm volatile("mma.sync.aligned.m16n8k32.row.col.s32.s8.s8.s32 "
                 "{%0,%1,%2,%3}, {%4,%5,%6,%7}, {%8,%9}, {%0,%1,%2,%3};"
                 : "+r"(c[0]), "+r"(c[1]), "+r"(c[2]), "+r"(c[3])
                 : "r"(a[0]), "r"(a[1]), "r"(a[2]), "r"(a[3]), "r"(b[0]), "r"(b[1]));
}

// ---------------- device scratch (static, allocation-free) ----------------
__device__ float g_partial[4*256];
__device__ float g_wscale[4];
__device__ __align__(16) signed char g_wq[DMODEL*DMODEL];
__device__ __align__(16) signed char g_wk[NKV*HD*DMODEL];
__device__ __align__(16) signed char g_wv[NKV*HD*DMODEL];
__device__ __align__(16) signed char g_wo[DMODEL*DMODEL];
__device__ __align__(16) signed char g_xq0[NTOK*DMODEL];
__device__ __align__(16) signed char g_xq1[NTOK*DMODEL];
__device__ __align__(16) signed char g_xq2[NTOK*DMODEL];
__device__ __align__(16) signed char g_xqo[NTOK*DMODEL];
__device__ float g_xs0[NTOK];
__device__ float g_xs1[NTOK];
__device__ float g_xs2[NTOK];
__device__ float g_xso[NTOK];
__device__ float g_projq[NTOK*DMODEL];     // [token, h*64+d]
__device__ float g_projk[NTOK*NKV*HD];     // [token, kv*64+d]
__device__ float g_projv[NTOK*NKV*HD];
__device__ float g_attn[NTOK*DMODEL];      // [token, h*64+d]

// ---------------- weight abs-mean: 4 matrices in one launch ----------------
__global__ void absum_all(const float* __restrict__ w0, const float* __restrict__ w1,
                          const float* __restrict__ w2, const float* __restrict__ w3) {
    __shared__ float red[256];
    const float* ws[4] = {w0, w1, w2, w3};
    const int    ns[4] = {DMODEL*DMODEL, NKV*HD*DMODEL, NKV*HD*DMODEL, DMODEL*DMODEL};
    int k = blockIdx.y;
    const float* w = ws[k];
    int n = ns[k];
    int tid = threadIdx.x;
    float s = 0.f;
    for (int i = blockIdx.x*256 + tid; i < n; i += 256*256) s += fabsf(w[i]);
    red[tid] = s; __syncthreads();
    for (int st = 128; st > 0; st >>= 1) { if (tid < st) red[tid] += red[tid+st]; __syncthreads(); }
    if (tid == 0) g_partial[k*256 + blockIdx.x] = red[0];
}

__global__ void finalize_wscale() {
    __shared__ float red[256];
    int tid = threadIdx.x;
    const float ninv[4] = {1.f/(2048.f*2048.f), 1.f/(512.f*2048.f),
                           1.f/(512.f*2048.f), 1.f/(2048.f*2048.f)};
    for (int k = 0; k < 4; k++) {
        red[tid] = g_partial[k*256 + tid]; __syncthreads();
        for (int st = 128; st > 0; st >>= 1) { if (tid < st) red[tid] += red[tid+st]; __syncthreads(); }
        if (tid == 0) g_wscale[k] = fmaxf(red[0]*ninv[k], 1e-5f);
        __syncthreads();
    }
}

// ---------------- ternary weight quant: 4 matrices in one launch ----------------
__global__ void quant_all(const float* __restrict__ w0, const float* __restrict__ w1,
                          const float* __restrict__ w2, const float* __restrict__ w3,
                          signed char* o0, signed char* o1, signed char* o2v, signed char* o3) {
    const float* ws[4] = {w0, w1, w2, w3};
    signed char* os[4] = {o0, o1, o2v, o3};
    const int    ns[4] = {DMODEL*DMODEL, NKV*HD*DMODEL, NKV*HD*DMODEL, DMODEL*DMODEL};
    int k = blockIdx.y;
    const float* w = ws[k];
    signed char* o = os[k];
    int n = ns[k];
    float inv = 1.f / g_wscale[k];
    for (int i = blockIdx.x*blockDim.x + threadIdx.x; i < n; i += gridDim.x*blockDim.x) {
        float q = rintf(w[i]*inv);
        q = fminf(fmaxf(q, -1.f), 1.f);
        o[i] = (signed char)q;
    }
}

// ---------------- activation quant (rmsnorm + absmax int8), registers + packed stores ----------------
__global__ void act_quant(const float* __restrict__ x,
                          const float* g0, const float* g1, const float* g2,
                          signed char* xq0, signed char* xq1, signed char* xq2,
                          float* s0, float* s1, float* s2) {
    __shared__ float red[256];
    int row = blockIdx.x, tid = threadIdx.x;
    const float4* xp = (const float4*)(x + (size_t)row*DMODEL);
    // thread owns elements [tid*8, tid*8+8)
    float4 xa = xp[tid*2], xb = xp[tid*2+1];
    float xv[8] = {xa.x, xa.y, xa.z, xa.w, xb.x, xb.y, xb.z, xb.w};
    float ss = 0.f;
    #pragma unroll
    for (int l = 0; l < 8; l++) ss += xv[l]*xv[l];
    red[tid] = ss; __syncthreads();
    for (int st = 128; st > 0; st >>= 1) { if (tid < st) red[tid] += red[tid+st]; __syncthreads(); }
    float rinv = rsqrtf(red[0]*(1.f/(float)DMODEL) + 1e-6f);

    const float* gs[3] = {g0, g1, g2};
    signed char* xqs[3] = {xq0, xq1, xq2};
    float* scs[3] = {s0, s1, s2};
    for (int vI = 0; vI < 3; vI++) {
        const float* g = gs[vI];
        if (!g) continue;
        __syncthreads();
        const float4* gp = (const float4*)g;
        float4 ga = gp[tid*2], gb = gp[tid*2+1];
        float gv[8] = {ga.x, ga.y, ga.z, ga.w, gb.x, gb.y, gb.z, gb.w};
        float amax = 0.f, xn[8];
        #pragma unroll
        for (int l = 0; l < 8; l++) {
            float v = xv[l]*rinv*gv[l];
            xn[l] = v; amax = fmaxf(amax, fabsf(v));
        }
        red[tid] = amax; __syncthreads();
        for (int st = 128; st > 0; st >>= 1) { if (tid < st) red[tid] = fmaxf(red[tid], red[tid+st]); __syncthreads(); }
        float sc = fmaxf(red[0], 1e-5f);
        float qf = 127.f/sc;
        int qi[8];
        #pragma unroll
        for (int l = 0; l < 8; l++) {
            int q = __float2int_rn(xn[l]*qf);
            qi[l] = max(-128, min(127, q));
        }
        unsigned lo = (qi[0]&0xFF) | ((qi[1]&0xFF)<<8) | ((qi[2]&0xFF)<<16) | ((unsigned)qi[3]<<24);
        unsigned hi = (qi[4]&0xFF) | ((qi[5]&0xFF)<<8) | ((qi[6]&0xFF)<<16) | ((unsigned)qi[7]<<24);
        int2 pk; pk.x = (int)lo; pk.y = (int)hi;
        *(int2*)(xqs[vI] + (size_t)row*DMODEL + tid*8) = pk;
        if (tid == 0) scs[vI][row] = sc;
    }
}

// ---------------- int8 tensor-core GEMM core (mma.sync m16n8k32) ----------------
__device__ __forceinline__ void gemm_imma_body(const signed char* A, const signed char* B,
                                               const float* xsc, int widx,
                                               float* C, int N, int m0, int n0) {
    __shared__ alignas(16) int4 As4[128*8];
    __shared__ alignas(16) int4 Bs4[128*8];
    const int K = 2048;
    int tid = threadIdx.x;
    int lane = tid & 31, warp = tid >> 5;
    int warp_m = warp >> 2, warp_n = warp & 3;     // 2 x 4

    uint32_t asb = (uint32_t)__cvta_generic_to_shared(As4);
    uint32_t bsb = (uint32_t)__cvta_generic_to_shared(Bs4);

    int g = lane >> 3, lr = lane & 7;
    int rowA_base = warp_m*64 + (g&1)*8 + lr;
    int rowB_base = warp_n*32 + (g>>1)*8 + lr;
    int acolg = g >> 1, bcolg = g & 1;
    int grow = tid >> 3, gcol = tid & 7;

    int c[4][4][4];
    #pragma unroll
    for (int mt = 0; mt < 4; mt++)
        #pragma unroll
        for (int nt = 0; nt < 4; nt++)
            #pragma unroll
            for (int i = 0; i < 4; i++) c[mt][nt][i] = 0;

    for (int kb = 0; kb < K/128; kb++) {
        __syncthreads();
        #pragma unroll
        for (int l = 0; l < 4; l++) {
            int row = grow + l*32;
            const int4* ag = (const int4*)(A + (size_t)(m0 + row)*K + kb*128 + gcol*16);
            As4[row*8 + (gcol ^ (row & 7))] = *ag;
            const int4* bg = (const int4*)(B + (size_t)(n0 + row)*K + kb*128 + gcol*16);
            Bs4[row*8 + (gcol ^ (row & 7))] = *bg;
        }
        __syncthreads();
        #pragma unroll
        for (int kk = 0; kk < 4; kk++) {
            uint32_t a[4][4];
            #pragma unroll
            for (int mt = 0; mt < 4; mt++) {
                int rowA = rowA_base + mt*16;
                uint32_t addr = asb + (uint32_t)(rowA*128 + (((kk*2 + acolg) ^ lr) << 4));
                ldsm4(a[mt][0], a[mt][1], a[mt][2], a[mt][3], addr);
            }
            uint32_t bfr[4][2];
            #pragma unroll
            for (int nt2 = 0; nt2 < 2; nt2++) {
                int rowB = rowB_base + nt2*16;
                uint32_t addr = bsb + (uint32_t)(rowB*128 + (((kk*2 + bcolg) ^ lr) << 4));
                uint32_t r0, r1, r2, r3;
                ldsm4(r0, r1, r2, r3, addr);
                bfr[nt2*2][0] = r0;   bfr[nt2*2][1] = r1;
                bfr[nt2*2+1][0] = r2; bfr[nt2*2+1][1] = r3;
            }
            #pragma unroll
            for (int mt = 0; mt < 4; mt++)
                #pragma unroll
                for (int nt = 0; nt < 4; nt++)
                    imma16832(c[mt][nt], a[mt], bfr[nt]);
        }
    }

    float wsc = g_wscale[widx] * (1.f/127.f);
    int lane4 = lane >> 2, lanec = (lane & 3)*2;
    #pragma unroll
    for (int mt = 0; mt < 4; mt++) {
        int r0 = m0 + warp_m*64 + mt*16 + lane4;
        float s0 = wsc * xsc[r0];
        float s1 = wsc * xsc[r0 + 8];
        #pragma unroll
        for (int nt = 0; nt < 4; nt++) {
            int col = n0 + warp_n*32 + nt*8 + lanec;
            float2 v0, v1;
            v0.x = c[mt][nt][0]*s0; v0.y = c[mt][nt][1]*s0;
            v1.x = c[mt][nt][2]*s1; v1.y = c[mt][nt][3]*s1;
            *(float2*)&C[(size_t)r0*N + col] = v0;
            *(float2*)&C[(size_t)(r0+8)*N + col] = v1;
        }
    }
}

// fused Q/K/V projection GEMM: grid.x = 16(q) + 4(k) + 4(v) = 24
__global__ __launch_bounds__(256)
void gemm_qkv(const signed char* __restrict__ A0, const signed char* __restrict__ A1,
              const signed char* __restrict__ A2,
              const signed char* __restrict__ B0, const signed char* __restrict__ B1,
              const signed char* __restrict__ B2,
              const float* __restrict__ xs0, const float* __restrict__ xs1,
              const float* __restrict__ xs2,
              float* __restrict__ C0, float* __restrict__ C1, float* __restrict__ C2) {
    int bx = blockIdx.x;
    int m0 = blockIdx.y*128;
    if (bx < 16) {
        gemm_imma_body(A0, B0, xs0, 0, C0, DMODEL, m0, bx*128);
    } else if (bx < 20) {
        gemm_imma_body(A1, B1, xs1, 1, C1, NKV*HD, m0, (bx-16)*128);
    } else {
        gemm_imma_body(A2, B2, xs2, 2, C2, NKV*HD, m0, (bx-20)*128);
    }
}

// single GEMM (output projection)
__global__ __launch_bounds__(256)
void gemm_imma(const signed char* __restrict__ A, const signed char* __restrict__ B,
               const float* __restrict__ xsc, int widx,
               float* __restrict__ C, int N) {
    gemm_imma_body(A, B, xsc, widx, C, N, blockIdx.y*128, blockIdx.x*128);
}

// ---------------- RoPE (in place), q + k in one launch ----------------
__global__ void rope_all(float* __restrict__ bq, float* __restrict__ bk,
                         const float* __restrict__ cs, const float* __restrict__ sn) {
    int idx = blockIdx.x*blockDim.x + threadIdx.x;
    const int qtot = NTOK*NH*32;
    float* buf; int nh;
    if (idx < qtot) { buf = bq; nh = NH; }
    else            { buf = bk; nh = NKV; idx -= qtot; }
    int i = idx & 31;
    int h = (idx >> 5) % nh;
    int tok = (idx >> 5) / nh;
    int t = tok & (SEQ - 1);
    float* p = buf + (size_t)tok*(nh*HD) + h*HD;
    float c0 = cs[t*HD + i],      s0 = sn[t*HD + i];
    float c1 = cs[t*HD + 32 + i], s1 = sn[t*HD + 32 + i];
    float a = p[i], b = p[32 + i];
    p[i]      = a*c0 - b*s0;
    p[32 + i] = b*c1 + a*s1;
}

// ---------------- causal flash attention, GQA (n_rep=4), f32x2 register-tiled ----------------
// grid (SEQ/128, NH, B); 256 threads; dyn smem = 102400 B; 2 CTA/SM
// Q pre-scaled by 0.125*log2(e); softmax runs in exp2 domain.
#define QSC (0.125f * 1.4426950408889634f)
__global__ __launch_bounds__(256, 2)
void attn_kernel(const float* __restrict__ Q, const float* __restrict__ K,
                 const float* __restrict__ V, float* __restrict__ O) {
    extern __shared__ float sm[];
    float* qT  = sm;                   // [64][132]  d-major: qT[d][i], i 0..127
    float* kT  = sm + 64*132;          // [64][68]   d-major: kT[d][j], j 0..63
    float* vs  = kT + 64*68;           // [64][68]   row-major: vs[j][d]
    float* psT = vs + 64*68;           // [64][132]  j-major: psT[j][i]
    int tid = threadIdx.x;
    int qt = blockIdx.x, h = blockIdx.y, b = blockIdx.z;
    int q0 = qt*128, kvh = h >> 2;
    int tx = tid & 15, ty = tid >> 4;
    const float* Qb = Q + (size_t)(b*SEQ + q0)*DMODEL + h*HD;
    const float* Kb = K + (size_t)(b*SEQ)*(NKV*HD) + kvh*HD;
    const float* Vb = V + (size_t)(b*SEQ)*(NKV*HD) + kvh*HD;

    // load Q tile transposed (128 rows x 64 d -> qT[d][i]), pre-scaled
    #pragma unroll
    for (int l = 0; l < 8; l++) {
        int idx = tid + l*256;            // 0..2047
        int r = idx >> 4, c4 = idx & 15;
        float4 f = *(const float4*)&Qb[(size_t)r*DMODEL + c4*4];
        qT[(c4*4+0)*132 + r] = f.x*QSC;
        qT[(c4*4+1)*132 + r] = f.y*QSC;
        qT[(c4*4+2)*132 + r] = f.z*QSC;
        qT[(c4*4+3)*132 + r] = f.w*QSC;
    }

    float m_i[8], l_i[8];
    unsigned long long o2[4][4];          // [row-pair][dd], rows (ty*8+2a, ty*8+2a+1)
    #pragma unroll
    for (int i = 0; i < 8; i++) { m_i[i] = -1e30f; l_i[i] = 0.f; }
    #pragma unroll
    for (int a = 0; a < 4; a++)
        #pragma unroll
        for (int d = 0; d < 4; d++) o2[a][d] = 0ull;

    int ktmax = 2*qt + 1;
    for (int kt = 0; kt <= ktmax; kt++) {
        int j0 = kt*64;
        __syncthreads();   // previous PV done before overwriting kT/vs
        // load K transposed + V straight (64 x 64 each)
        #pragma unroll
        for (int l = 0; l < 4; l++) {
            int idx = tid + l*256;        // 0..1023
            int r = idx >> 4, c4 = idx & 15;
            float4 f = *(const float4*)&Kb[(size_t)(j0 + r)*(NKV*HD) + c4*4];
            kT[(c4*4+0)*68 + r] = f.x;
            kT[(c4*4+1)*68 + r] = f.y;
            kT[(c4*4+2)*68 + r] = f.z;
            kT[(c4*4+3)*68 + r] = f.w;
            float4 g = *(const float4*)&Vb[(size_t)(j0 + r)*(NKV*HD) + c4*4];
            *(float4*)&vs[r*68 + c4*4] = g;
        }
        __syncthreads();

        // ---- S = Q @ K^T : s2[row-pair a][jj] over d (already log2e-scaled) ----
        unsigned long long s2[4][4];
        #pragma unroll
        for (int a = 0; a < 4; a++)
            #pragma unroll
            for (int j = 0; j < 4; j++) s2[a][j] = 0ull;

        #pragma unroll 4
        for (int d = 0; d < 64; d++) {
            ulonglong2 qa = *(const ulonglong2*)&qT[d*132 + ty*8];
            ulonglong2 qb2 = *(const ulonglong2*)&qT[d*132 + ty*8 + 4];
            float4 kf = *(const float4*)&kT[d*68 + tx*4];
            unsigned long long k0 = pack2(kf.x, kf.x);
            unsigned long long k1 = pack2(kf.y, kf.y);
            unsigned long long k2 = pack2(kf.z, kf.z);
            unsigned long long k3 = pack2(kf.w, kf.w);
            fma2(s2[0][0], qa.x, k0);  fma2(s2[0][1], qa.x, k1);
            fma2(s2[0][2], qa.x, k2);  fma2(s2[0][3], qa.x, k3);
            fma2(s2[1][0], qa.y, k0);  fma2(s2[1][1], qa.y, k1);
            fma2(s2[1][2], qa.y, k2);  fma2(s2[1][3], qa.y, k3);
            fma2(s2[2][0], qb2.x, k0); fma2(s2[2][1], qb2.x, k1);
            fma2(s2[2][2], qb2.x, k2); fma2(s2[2][3], qb2.x, k3);
            fma2(s2[3][0], qb2.y, k0); fma2(s2[3][1], qb2.y, k1);
            fma2(s2[3][2], qb2.y, k2); fma2(s2[3][3], qb2.y, k3);
        }

        // ---- softmax (online, exp2 domain) ----
        float sc[8][4];
        #pragma unroll
        for (int a = 0; a < 4; a++)
            #pragma unroll
            for (int j = 0; j < 4; j++)
                unpack2(s2[a][j], sc[2*a][j], sc[2*a+1][j]);

        bool needmask = (kt >= 2*qt);
        float corr[8];
        #pragma unroll
        for (int ii = 0; ii < 8; ii++) {
            int ig = q0 + ty*8 + ii;
            float tm = -1e30f;
            if (needmask) {
                #pragma unroll
                for (int jj = 0; jj < 4; jj++) {
                    float v = sc[ii][jj];
                    if (j0 + tx*4 + jj > ig) v = -1e30f;
                    sc[ii][jj] = v;
                    tm = fmaxf(tm, v);
                }
            } else {
                #pragma unroll
                for (int jj = 0; jj < 4; jj++) tm = fmaxf(tm, sc[ii][jj]);
            }
            tm = fmaxf(tm, __shfl_xor_sync(0xffffffffu, tm, 1));
            tm = fmaxf(tm, __shfl_xor_sync(0xffffffffu, tm, 2));
            tm = fmaxf(tm, __shfl_xor_sync(0xffffffffu, tm, 4));
            tm = fmaxf(tm, __shfl_xor_sync(0xffffffffu, tm, 8));
            float nm = fmaxf(m_i[ii], tm);
            corr[ii] = ex2(m_i[ii] - nm);
            m_i[ii] = nm;
            float ts = 0.f;
            #pragma unroll
            for (int jj = 0; jj < 4; jj++) {
                float p = ex2(sc[ii][jj] - nm);
                sc[ii][jj] = p; ts += p;
            }
            ts += __shfl_xor_sync(0xffffffffu, ts, 1);
            ts += __shfl_xor_sync(0xffffffffu, ts, 2);
            ts += __shfl_xor_sync(0xffffffffu, ts, 4);
            ts += __shfl_xor_sync(0xffffffffu, ts, 8);
            l_i[ii] = l_i[ii]*corr[ii] + ts;
        }
        // rescale O accumulators (packed row-pairs)
        #pragma unroll
        for (int a = 0; a < 4; a++) {
            unsigned long long c2 = pack2(corr[2*a], corr[2*a+1]);
            #pragma unroll
            for (int d = 0; d < 4; d++) o2[a][d] = mul2(o2[a][d], c2);
        }
        // store P transposed: psT[j][i]
        #pragma unroll
        for (int jj = 0; jj < 4; jj++)
            #pragma unroll
            for (int ii = 0; ii < 8; ii++)
                psT[(tx*4+jj)*132 + ty*8 + ii] = sc[ii][jj];
        __syncthreads();

        // ---- O += P @ V : reduce over j ----
        #pragma unroll 4
        for (int j = 0; j < 64; j++) {
            ulonglong2 pa = *(const ulonglong2*)&psT[j*132 + ty*8];
            ulonglong2 pb = *(const ulonglong2*)&psT[j*132 + ty*8 + 4];
            float4 vf = *(const float4*)&vs[j*68 + tx*4];
            unsigned long long v0 = pack2(vf.x, vf.x);
            unsigned long long v1 = pack2(vf.y, vf.y);
            unsigned long long v2 = pack2(vf.z, vf.z);
            unsigned long long v3 = pack2(vf.w, vf.w);
            fma2(o2[0][0], pa.x, v0);  fma2(o2[0][1], pa.x, v1);
            fma2(o2[0][2], pa.x, v2);  fma2(o2[0][3], pa.x, v3);
            fma2(o2[1][0], pa.y, v0);  fma2(o2[1][1], pa.y, v1);
            fma2(o2[1][2], pa.y, v2);  fma2(o2[1][3], pa.y, v3);
            fma2(o2[2][0], pb.x, v0);  fma2(o2[2][1], pb.x, v1);
            fma2(o2[2][2], pb.x, v2);  fma2(o2[2][3], pb.x, v3);
            fma2(o2[3][0], pb.y, v0);  fma2(o2[3][1], pb.y, v1);
            fma2(o2[3][2], pb.y, v2);  fma2(o2[3][3], pb.y, v3);
        }
    }

    // ---- epilogue ----
    float* Ob = O + (size_t)(b*SEQ + q0)*DMODEL + h*HD;
    #pragma unroll
    for (int a = 0; a < 4; a++) {
        float lo[4], hi[4];
        #pragma unroll
        for (int d = 0; d < 4; d++) unpack2(o2[a][d], lo[d], hi[d]);
        float inv0 = 1.f / l_i[2*a];
        float inv1 = 1.f / l_i[2*a+1];
        float4 f0, f1;
        f0.x = lo[0]*inv0; f0.y = lo[1]*inv0; f0.z = lo[2]*inv0; f0.w = lo[3]*inv0;
        f1.x = hi[0]*inv1; f1.y = hi[1]*inv1; f1.z = hi[2]*inv1; f1.w = hi[3]*inv1;
        *(float4*)&Ob[(size_t)(ty*8 + 2*a    )*DMODEL + tx*4] = f0;
        *(float4*)&Ob[(size_t)(ty*8 + 2*a + 1)*DMODEL + tx*4] = f1;
    }
}

// ---------------- launch ----------------
extern "C" void kernel_launch(void* const* d_in, const int* in_sizes, int n_in,
                              void* d_out, int out_size) {
    const float* x   = (const float*)d_in[0];
    const float* cs  = (const float*)d_in[1];
    const float* sn  = (const float*)d_in[2];
    const float* wq  = (const float*)d_in[3];
    const float* wk  = (const float*)d_in[4];
    const float* wv  = (const float*)d_in[5];
    const float* wo  = (const float*)d_in[6];
    const float* gq  = (const float*)d_in[7];
    const float* gk  = (const float*)d_in[8];
    const float* gv  = (const float*)d_in[9];
    const float* go  = (const float*)d_in[10];
    float* out = (float*)d_out;

    signed char *wq_q, *wk_q, *wv_q, *wo_q, *xq0, *xq1, *xq2, *xqo;
    float *xs0, *xs1, *xs2, *xso, *projq, *projk, *projv, *attnb;
    cudaGetSymbolAddress((void**)&wq_q, g_wq);
    cudaGetSymbolAddress((void**)&wk_q, g_wk);
    cudaGetSymbolAddress((void**)&wv_q, g_wv);
    cudaGetSymbolAddress((void**)&wo_q, g_wo);
    cudaGetSymbolAddress((void**)&xq0, g_xq0);
    cudaGetSymbolAddress((void**)&xq1, g_xq1);
    cudaGetSymbolAddress((void**)&xq2, g_xq2);
    cudaGetSymbolAddress((void**)&xqo, g_xqo);
    cudaGetSymbolAddress((void**)&xs0, g_xs0);
    cudaGetSymbolAddress((void**)&xs1, g_xs1);
    cudaGetSymbolAddress((void**)&xs2, g_xs2);
    cudaGetSymbolAddress((void**)&xso, g_xso);
    cudaGetSymbolAddress((void**)&projq, g_projq);
    cudaGetSymbolAddress((void**)&projk, g_projk);
    cudaGetSymbolAddress((void**)&projv, g_projv);
    cudaGetSymbolAddress((void**)&attnb, g_attn);

    cudaFuncSetAttribute(attn_kernel, cudaFuncAttributeMaxDynamicSharedMemorySize, 102400);

    // weight scales + ternary quant (fused launches)
    absum_all<<<dim3(256, 4), 256>>>(wq, wk, wv, wo);
    finalize_wscale<<<1, 256>>>();
    quant_all<<<dim3(1024, 4), 256>>>(wq, wk, wv, wo, wq_q, wk_q, wv_q, wo_q);

    // activation quant (3 projections share x row + rmsnorm stat)
    act_quant<<<NTOK, 256>>>(x, gq, gk, gv, xq0, xq1, xq2, xs0, xs1, xs2);

    // projections: fused Q/K/V int8 tensor GEMM in one launch
    gemm_qkv<<<dim3(24, NTOK/128), 256>>>(xq0, xq1, xq2, wq_q, wk_q, wv_q,
                                          xs0, xs1, xs2, projq, projk, projv);

    // rope (q + k fused)
    rope_all<<<(NTOK*(NH+NKV)*32)/256, 256>>>(projq, projk, cs, sn);

    // attention
    attn_kernel<<<dim3(SEQ/128, NH, BATCH), 256, 102400>>>(projq, projk, projv, attnb);

    // output bitlinear
    act_quant<<<NTOK, 256>>>(attnb, go, nullptr, nullptr, xqo, nullptr, nullptr, xso, nullptr, nullptr);
    gemm_imma<<<dim3(DMODEL/128, NTOK/128), 256>>>(xqo, wo_q, xso, 3, out, DMODEL);
}

// round 8
// speedup vs baseline: 1.1179x; 1.0192x over previous
#include <cuda_runtime.h>
#include <cuda_bf16.h>
#include <cstdint>

// Problem constants (fixed shapes)
#define BATCH 2
#define SEQ   2048
#define DMODEL 2048
#define NH    32
#define NKV   8
#define HD    64
#define NTOK  (BATCH*SEQ)          // 4096

// ---------------- f32x2 packed math helpers ----------------
__device__ __forceinline__ void fma2(unsigned long long &d, unsigned long long a, unsigned long long b) {
    asm("fma.rn.f32x2 %0, %1, %2, %0;" : "+l"(d) : "l"(a), "l"(b));
}
__device__ __forceinline__ unsigned long long mul2(unsigned long long a, unsigned long long b) {
    unsigned long long r;
    asm("mul.rn.f32x2 %0, %1, %2;" : "=l"(r) : "l"(a), "l"(b));
    return r;
}
__device__ __forceinline__ unsigned long long pack2(float lo, float hi) {
    unsigned long long r;
    asm("mov.b64 %0, {%1, %2};" : "=l"(r) : "f"(lo), "f"(hi));
    return r;
}
__device__ __forceinline__ void unpack2(unsigned long long v, float &lo, float &hi) {
    asm("mov.b64 {%0, %1}, %2;" : "=f"(lo), "=f"(hi) : "l"(v));
}
__device__ __forceinline__ float ex2(float x) {
    float r;
    asm("ex2.approx.ftz.f32 %0, %1;" : "=f"(r) : "f"(x));
    return r;
}

// ---------------- mma.sync / ldmatrix / cp.async helpers ----------------
__device__ __forceinline__ void ldsm4(uint32_t &r0, uint32_t &r1, uint32_t &r2, uint32_t &r3, uint32_t addr) {
    asm volatile("ldmatrix.sync.aligned.m8n8.x4.shared.b16 {%0,%1,%2,%3}, [%4];"
                 : "=r"(r0), "=r"(r1), "=r"(r2), "=r"(r3) : "r"(addr));
}
__device__ __forceinline__ void imma16832(int* c, const uint32_t* a, const uint32_t* b) {
    asm volatile("mma.sync.aligned.m16n8k32.row.col.s32.s8.s8.s32 "
                 "{%0,%1,%2,%3}, {%4,%5,%6,%7}, {%8,%9}, {%0,%1,%2,%3};"
                 : "+r"(c[0]), "+r"(c[1]), "+r"(c[2]), "+r"(c[3])
                 : "r"(a[0]), "r"(a[1]), "r"(a[2]), "r"(a[3]), "r"(b[0]), "r"(b[1]));
}
__device__ __forceinline__ void cp16(uint32_t dst, const void* src) {
    asm volatile("cp.async.cg.shared.global [%0], [%1], 16;" :: "r"(dst), "l"(src) : "memory");
}
#define CP_COMMIT() asm volatile("cp.async.commit_group;" ::: "memory")
#define CP_WAIT1()  asm volatile("cp.async.wait_group 1;" ::: "memory")
#define CP_WAIT0()  asm volatile("cp.async.wait_group 0;" ::: "memory")

// ---------------- device scratch (static, allocation-free) ----------------
__device__ float g_partial[4*256];
__device__ float g_wscale[4];
__device__ __align__(16) signed char g_wq[DMODEL*DMODEL];
__device__ __align__(16) signed char g_wk[NKV*HD*DMODEL];
__device__ __align__(16) signed char g_wv[NKV*HD*DMODEL];
__device__ __align__(16) signed char g_wo[DMODEL*DMODEL];
__device__ __align__(16) signed char g_xq0[NTOK*DMODEL];
__device__ __align__(16) signed char g_xq1[NTOK*DMODEL];
__device__ __align__(16) signed char g_xq2[NTOK*DMODEL];
__device__ __align__(16) signed char g_xqo[NTOK*DMODEL];
__device__ float g_xs0[NTOK];
__device__ float g_xs1[NTOK];
__device__ float g_xs2[NTOK];
__device__ float g_xso[NTOK];
__device__ float g_projq[NTOK*DMODEL];     // [token, h*64+d]
__device__ float g_projk[NTOK*NKV*HD];     // [token, kv*64+d]
__device__ float g_projv[NTOK*NKV*HD];
__device__ float g_attn[NTOK*DMODEL];      // [token, h*64+d]

// ---------------- weight abs-mean: 4 matrices in one launch ----------------
__global__ void absum_all(const float* __restrict__ w0, const float* __restrict__ w1,
                          const float* __restrict__ w2, const float* __restrict__ w3) {
    __shared__ float red[256];
    const float* ws[4] = {w0, w1, w2, w3};
    const int    ns[4] = {DMODEL*DMODEL, NKV*HD*DMODEL, NKV*HD*DMODEL, DMODEL*DMODEL};
    int k = blockIdx.y;
    const float* w = ws[k];
    int n = ns[k];
    int tid = threadIdx.x;
    float s = 0.f;
    for (int i = blockIdx.x*256 + tid; i < n; i += 256*256) s += fabsf(w[i]);
    red[tid] = s; __syncthreads();
    for (int st = 128; st > 0; st >>= 1) { if (tid < st) red[tid] += red[tid+st]; __syncthreads(); }
    if (tid == 0) g_partial[k*256 + blockIdx.x] = red[0];
}

__global__ void finalize_wscale() {
    __shared__ float red[256];
    int tid = threadIdx.x;
    const float ninv[4] = {1.f/(2048.f*2048.f), 1.f/(512.f*2048.f),
                           1.f/(512.f*2048.f), 1.f/(2048.f*2048.f)};
    for (int k = 0; k < 4; k++) {
        red[tid] = g_partial[k*256 + tid]; __syncthreads();
        for (int st = 128; st > 0; st >>= 1) { if (tid < st) red[tid] += red[tid+st]; __syncthreads(); }
        if (tid == 0) g_wscale[k] = fmaxf(red[0]*ninv[k], 1e-5f);
        __syncthreads();
    }
}

// ---------------- ternary weight quant: 4 matrices in one launch ----------------
__global__ void quant_all(const float* __restrict__ w0, const float* __restrict__ w1,
                          const float* __restrict__ w2, const float* __restrict__ w3,
                          signed char* o0, signed char* o1, signed char* o2v, signed char* o3) {
    const float* ws[4] = {w0, w1, w2, w3};
    signed char* os[4] = {o0, o1, o2v, o3};
    const int    ns[4] = {DMODEL*DMODEL, NKV*HD*DMODEL, NKV*HD*DMODEL, DMODEL*DMODEL};
    int k = blockIdx.y;
    const float* w = ws[k];
    signed char* o = os[k];
    int n = ns[k];
    float inv = 1.f / g_wscale[k];
    for (int i = blockIdx.x*blockDim.x + threadIdx.x; i < n; i += gridDim.x*blockDim.x) {
        float q = rintf(w[i]*inv);
        q = fminf(fmaxf(q, -1.f), 1.f);
        o[i] = (signed char)q;
    }
}

// ---------------- activation quant (rmsnorm + absmax int8), registers + packed stores ----------------
__global__ void act_quant(const float* __restrict__ x,
                          const float* g0, const float* g1, const float* g2,
                          signed char* xq0, signed char* xq1, signed char* xq2,
                          float* s0, float* s1, float* s2) {
    __shared__ float red[256];
    int row = blockIdx.x, tid = threadIdx.x;
    const float4* xp = (const float4*)(x + (size_t)row*DMODEL);
    float4 xa = xp[tid*2], xb = xp[tid*2+1];
    float xv[8] = {xa.x, xa.y, xa.z, xa.w, xb.x, xb.y, xb.z, xb.w};
    float ss = 0.f;
    #pragma unroll
    for (int l = 0; l < 8; l++) ss += xv[l]*xv[l];
    red[tid] = ss; __syncthreads();
    for (int st = 128; st > 0; st >>= 1) { if (tid < st) red[tid] += red[tid+st]; __syncthreads(); }
    float rinv = rsqrtf(red[0]*(1.f/(float)DMODEL) + 1e-6f);

    const float* gs[3] = {g0, g1, g2};
    signed char* xqs[3] = {xq0, xq1, xq2};
    float* scs[3] = {s0, s1, s2};
    for (int vI = 0; vI < 3; vI++) {
        const float* g = gs[vI];
        if (!g) continue;
        __syncthreads();
        const float4* gp = (const float4*)g;
        float4 ga = gp[tid*2], gb = gp[tid*2+1];
        float gv[8] = {ga.x, ga.y, ga.z, ga.w, gb.x, gb.y, gb.z, gb.w};
        float amax = 0.f, xn[8];
        #pragma unroll
        for (int l = 0; l < 8; l++) {
            float v = xv[l]*rinv*gv[l];
            xn[l] = v; amax = fmaxf(amax, fabsf(v));
        }
        red[tid] = amax; __syncthreads();
        for (int st = 128; st > 0; st >>= 1) { if (tid < st) red[tid] = fmaxf(red[tid], red[tid+st]); __syncthreads(); }
        float sc = fmaxf(red[0], 1e-5f);
        float qf = 127.f/sc;
        int qi[8];
        #pragma unroll
        for (int l = 0; l < 8; l++) {
            int q = __float2int_rn(xn[l]*qf);
            qi[l] = max(-128, min(127, q));
        }
        unsigned lo = (qi[0]&0xFF) | ((qi[1]&0xFF)<<8) | ((qi[2]&0xFF)<<16) | ((unsigned)qi[3]<<24);
        unsigned hi = (qi[4]&0xFF) | ((qi[5]&0xFF)<<8) | ((qi[6]&0xFF)<<16) | ((unsigned)qi[7]<<24);
        int2 pk; pk.x = (int)lo; pk.y = (int)hi;
        *(int2*)(xqs[vI] + (size_t)row*DMODEL + tid*8) = pk;
        if (tid == 0) scs[vI][row] = sc;
    }
}

// ---------------- int8 tensor-core GEMM core, cp.async double-buffered ----------------
// dynamic smem: A bufs 2x32KB? no: A 2x16KB + B 2x16KB = 64KB
__device__ __forceinline__ void gemm_imma_body(const signed char* A, const signed char* B,
                                               const float* xsc, int widx,
                                               float* C, int N, int m0, int n0) {
    extern __shared__ __align__(16) int4 gsm[];
    // layout: As4 buf0 [0,1024), buf1 [1024,2048); Bs4 buf0 [2048,3072), buf1 [3072,4096)
    const int K = 2048;
    int tid = threadIdx.x;
    int lane = tid & 31, warp = tid >> 5;
    int warp_m = warp >> 2, warp_n = warp & 3;     // 2 x 4

    uint32_t sb = (uint32_t)__cvta_generic_to_shared(gsm);

    int g = lane >> 3, lr = lane & 7;
    int rowA_base = warp_m*64 + (g&1)*8 + lr;
    int rowB_base = warp_n*32 + (g>>1)*8 + lr;
    int acolg = g >> 1, bcolg = g & 1;
    int grow = tid >> 3, gcol = tid & 7;

    // per-thread smem write offsets (int4 index within a buffer)
    int c[4][4][4];
    #pragma unroll
    for (int mt = 0; mt < 4; mt++)
        #pragma unroll
        for (int nt = 0; nt < 4; nt++)
            #pragma unroll
            for (int i = 0; i < 4; i++) c[mt][nt][i] = 0;

    // prefetch kb = 0 into buf 0
    {
        #pragma unroll
        for (int l = 0; l < 4; l++) {
            int row = grow + l*32;
            uint32_t da = sb + (uint32_t)((0*1024 + row*8 + (gcol ^ (row & 7)))*16);
            cp16(da, A + (size_t)(m0 + row)*K + gcol*16);
            uint32_t db = sb + (uint32_t)(((2048) + 0*1024 + row*8 + (gcol ^ (row & 7)))*16);
            cp16(db, B + (size_t)(n0 + row)*K + gcol*16);
        }
        CP_COMMIT();
    }

    for (int kb = 0; kb < 16; kb++) {
        int buf = kb & 1;
        if (kb < 15) {
            int nb = buf ^ 1;
            #pragma unroll
            for (int l = 0; l < 4; l++) {
                int row = grow + l*32;
                uint32_t da = sb + (uint32_t)((nb*1024 + row*8 + (gcol ^ (row & 7)))*16);
                cp16(da, A + (size_t)(m0 + row)*K + (kb+1)*128 + gcol*16);
                uint32_t db = sb + (uint32_t)((2048 + nb*1024 + row*8 + (gcol ^ (row & 7)))*16);
                cp16(db, B + (size_t)(n0 + row)*K + (kb+1)*128 + gcol*16);
            }
            CP_COMMIT();
            CP_WAIT1();
        } else {
            CP_WAIT0();
        }
        __syncthreads();

        uint32_t asb = sb + (uint32_t)(buf*1024*16);
        uint32_t bsb = sb + (uint32_t)((2048 + buf*1024)*16);
        #pragma unroll
        for (int kk = 0; kk < 4; kk++) {
            uint32_t a[4][4];
            #pragma unroll
            for (int mt = 0; mt < 4; mt++) {
                int rowA = rowA_base + mt*16;
                uint32_t addr = asb + (uint32_t)(rowA*128 + (((kk*2 + acolg) ^ lr) << 4));
                ldsm4(a[mt][0], a[mt][1], a[mt][2], a[mt][3], addr);
            }
            uint32_t bfr[4][2];
            #pragma unroll
            for (int nt2 = 0; nt2 < 2; nt2++) {
                int rowB = rowB_base + nt2*16;
                uint32_t addr = bsb + (uint32_t)(rowB*128 + (((kk*2 + bcolg) ^ lr) << 4));
                uint32_t r0, r1, r2, r3;
                ldsm4(r0, r1, r2, r3, addr);
                bfr[nt2*2][0] = r0;   bfr[nt2*2][1] = r1;
                bfr[nt2*2+1][0] = r2; bfr[nt2*2+1][1] = r3;
            }
            #pragma unroll
            for (int mt = 0; mt < 4; mt++)
                #pragma unroll
                for (int nt = 0; nt < 4; nt++)
                    imma16832(c[mt][nt], a[mt], bfr[nt]);
        }
        __syncthreads();
    }

    float wsc = g_wscale[widx] * (1.f/127.f);
    int lane4 = lane >> 2, lanec = (lane & 3)*2;
    #pragma unroll
    for (int mt = 0; mt < 4; mt++) {
        int r0 = m0 + warp_m*64 + mt*16 + lane4;
        float s0 = wsc * xsc[r0];
        float s1 = wsc * xsc[r0 + 8];
        #pragma unroll
        for (int nt = 0; nt < 4; nt++) {
            int col = n0 + warp_n*32 + nt*8 + lanec;
            float2 v0, v1;
            v0.x = c[mt][nt][0]*s0; v0.y = c[mt][nt][1]*s0;
            v1.x = c[mt][nt][2]*s1; v1.y = c[mt][nt][3]*s1;
            *(float2*)&C[(size_t)r0*N + col] = v0;
            *(float2*)&C[(size_t)(r0+8)*N + col] = v1;
        }
    }
}

// fused Q/K/V projection GEMM: grid.x = 16(q) + 4(k) + 4(v) = 24
__global__ __launch_bounds__(256)
void gemm_qkv(const signed char* __restrict__ A0, const signed char* __restrict__ A1,
              const signed char* __restrict__ A2,
              const signed char* __restrict__ B0, const signed char* __restrict__ B1,
              const signed char* __restrict__ B2,
              const float* __restrict__ xs0, const float* __restrict__ xs1,
              const float* __restrict__ xs2,
              float* __restrict__ C0, float* __restrict__ C1, float* __restrict__ C2) {
    int bx = blockIdx.x;
    int m0 = blockIdx.y*128;
    if (bx < 16) {
        gemm_imma_body(A0, B0, xs0, 0, C0, DMODEL, m0, bx*128);
    } else if (bx < 20) {
        gemm_imma_body(A1, B1, xs1, 1, C1, NKV*HD, m0, (bx-16)*128);
    } else {
        gemm_imma_body(A2, B2, xs2, 2, C2, NKV*HD, m0, (bx-20)*128);
    }
}

// single GEMM (output projection)
__global__ __launch_bounds__(256)
void gemm_imma(const signed char* __restrict__ A, const signed char* __restrict__ B,
               const float* __restrict__ xsc, int widx,
               float* __restrict__ C, int N) {
    gemm_imma_body(A, B, xsc, widx, C, N, blockIdx.y*128, blockIdx.x*128);
}

// ---------------- RoPE (in place), q + k in one launch ----------------
__global__ void rope_all(float* __restrict__ bq, float* __restrict__ bk,
                         const float* __restrict__ cs, const float* __restrict__ sn) {
    int idx = blockIdx.x*blockDim.x + threadIdx.x;
    const int qtot = NTOK*NH*32;
    float* buf; int nh;
    if (idx < qtot) { buf = bq; nh = NH; }
    else            { buf = bk; nh = NKV; idx -= qtot; }
    int i = idx & 31;
    int h = (idx >> 5) % nh;
    int tok = (idx >> 5) / nh;
    int t = tok & (SEQ - 1);
    float* p = buf + (size_t)tok*(nh*HD) + h*HD;
    float c0 = cs[t*HD + i],      s0 = sn[t*HD + i];
    float c1 = cs[t*HD + 32 + i], s1 = sn[t*HD + 32 + i];
    float a = p[i], b = p[32 + i];
    p[i]      = a*c0 - b*s0;
    p[32 + i] = b*c1 + a*s1;
}

// ---------------- causal flash attention, GQA (n_rep=4), f32x2 register-tiled ----------------
// grid (SEQ/128, NH, B); 256 threads; dyn smem = 102400 B; 2 CTA/SM
// LPT scheduling: qt reversed so longest CTAs launch first.
#define QSC (0.125f * 1.4426950408889634f)
__global__ __launch_bounds__(256, 2)
void attn_kernel(const float* __restrict__ Q, const float* __restrict__ K,
                 const float* __restrict__ V, float* __restrict__ O) {
    extern __shared__ float sm[];
    float* qT  = sm;                   // [64][132]  d-major: qT[d][i], i 0..127
    float* kT  = sm + 64*132;          // [64][68]   d-major: kT[d][j], j 0..63
    float* vs  = kT + 64*68;           // [64][68]   row-major: vs[j][d]
    float* psT = vs + 64*68;           // [64][132]  j-major: psT[j][i]
    int tid = threadIdx.x;
    int qt = (gridDim.x - 1) - blockIdx.x;   // LPT: long blocks first
    int h = blockIdx.y, b = blockIdx.z;
    int q0 = qt*128, kvh = h >> 2;
    int tx = tid & 15, ty = tid >> 4;
    const float* Qb = Q + (size_t)(b*SEQ + q0)*DMODEL + h*HD;
    const float* Kb = K + (size_t)(b*SEQ)*(NKV*HD) + kvh*HD;
    const float* Vb = V + (size_t)(b*SEQ)*(NKV*HD) + kvh*HD;

    // load Q tile transposed (128 rows x 64 d -> qT[d][i]), pre-scaled
    #pragma unroll
    for (int l = 0; l < 8; l++) {
        int idx = tid + l*256;            // 0..2047
        int r = idx >> 4, c4 = idx & 15;
        float4 f = *(const float4*)&Qb[(size_t)r*DMODEL + c4*4];
        qT[(c4*4+0)*132 + r] = f.x*QSC;
        qT[(c4*4+1)*132 + r] = f.y*QSC;
        qT[(c4*4+2)*132 + r] = f.z*QSC;
        qT[(c4*4+3)*132 + r] = f.w*QSC;
    }

    float m_i[8], l_i[8];
    unsigned long long o2[4][4];          // [row-pair][dd], rows (ty*8+2a, ty*8+2a+1)
    #pragma unroll
    for (int i = 0; i < 8; i++) { m_i[i] = -1e30f; l_i[i] = 0.f; }
    #pragma unroll
    for (int a = 0; a < 4; a++)
        #pragma unroll
        for (int d = 0; d < 4; d++) o2[a][d] = 0ull;

    int ktmax = 2*qt + 1;
    for (int kt = 0; kt <= ktmax; kt++) {
        int j0 = kt*64;
        __syncthreads();   // previous PV done before overwriting kT/vs
        // load K transposed + V straight (64 x 64 each)
        #pragma unroll
        for (int l = 0; l < 4; l++) {
            int idx = tid + l*256;        // 0..1023
            int r = idx >> 4, c4 = idx & 15;
            float4 f = *(const float4*)&Kb[(size_t)(j0 + r)*(NKV*HD) + c4*4];
            kT[(c4*4+0)*68 + r] = f.x;
            kT[(c4*4+1)*68 + r] = f.y;
            kT[(c4*4+2)*68 + r] = f.z;
            kT[(c4*4+3)*68 + r] = f.w;
            float4 g = *(const float4*)&Vb[(size_t)(j0 + r)*(NKV*HD) + c4*4];
            *(float4*)&vs[r*68 + c4*4] = g;
        }
        __syncthreads();

        // ---- S = Q @ K^T : s2[row-pair a][jj] over d (already log2e-scaled) ----
        unsigned long long s2[4][4];
        #pragma unroll
        for (int a = 0; a < 4; a++)
            #pragma unroll
            for (int j = 0; j < 4; j++) s2[a][j] = 0ull;

        #pragma unroll 4
        for (int d = 0; d < 64; d++) {
            ulonglong2 qa = *(const ulonglong2*)&qT[d*132 + ty*8];
            ulonglong2 qb2 = *(const ulonglong2*)&qT[d*132 + ty*8 + 4];
            float4 kf = *(const float4*)&kT[d*68 + tx*4];
            unsigned long long k0 = pack2(kf.x, kf.x);
            unsigned long long k1 = pack2(kf.y, kf.y);
            unsigned long long k2 = pack2(kf.z, kf.z);
            unsigned long long k3 = pack2(kf.w, kf.w);
            fma2(s2[0][0], qa.x, k0);  fma2(s2[0][1], qa.x, k1);
            fma2(s2[0][2], qa.x, k2);  fma2(s2[0][3], qa.x, k3);
            fma2(s2[1][0], qa.y, k0);  fma2(s2[1][1], qa.y, k1);
            fma2(s2[1][2], qa.y, k2);  fma2(s2[1][3], qa.y, k3);
            fma2(s2[2][0], qb2.x, k0); fma2(s2[2][1], qb2.x, k1);
            fma2(s2[2][2], qb2.x, k2); fma2(s2[2][3], qb2.x, k3);
            fma2(s2[3][0], qb2.y, k0); fma2(s2[3][1], qb2.y, k1);
            fma2(s2[3][2], qb2.y, k2); fma2(s2[3][3], qb2.y, k3);
        }

        // ---- softmax (online, exp2 domain) ----
        float sc[8][4];
        #pragma unroll
        for (int a = 0; a < 4; a++)
            #pragma unroll
            for (int j = 0; j < 4; j++)
                unpack2(s2[a][j], sc[2*a][j], sc[2*a+1][j]);

        bool needmask = (kt >= 2*qt);
        float corr[8];
        #pragma unroll
        for (int ii = 0; ii < 8; ii++) {
            int ig = q0 + ty*8 + ii;
            float tm = -1e30f;
            if (needmask) {
                #pragma unroll
                for (int jj = 0; jj < 4; jj++) {
                    float v = sc[ii][jj];
                    if (j0 + tx*4 + jj > ig) v = -1e30f;
                    sc[ii][jj] = v;
                    tm = fmaxf(tm, v);
                }
            } else {
                #pragma unroll
                for (int jj = 0; jj < 4; jj++) tm = fmaxf(tm, sc[ii][jj]);
            }
            tm = fmaxf(tm, __shfl_xor_sync(0xffffffffu, tm, 1));
            tm = fmaxf(tm, __shfl_xor_sync(0xffffffffu, tm, 2));
            tm = fmaxf(tm, __shfl_xor_sync(0xffffffffu, tm, 4));
            tm = fmaxf(tm, __shfl_xor_sync(0xffffffffu, tm, 8));
            float nm = fmaxf(m_i[ii], tm);
            corr[ii] = ex2(m_i[ii] - nm);
            m_i[ii] = nm;
            float ts = 0.f;
            #pragma unroll
            for (int jj = 0; jj < 4; jj++) {
                float p = ex2(sc[ii][jj] - nm);
                sc[ii][jj] = p; ts += p;
            }
            ts += __shfl_xor_sync(0xffffffffu, ts, 1);
            ts += __shfl_xor_sync(0xffffffffu, ts, 2);
            ts += __shfl_xor_sync(0xffffffffu, ts, 4);
            ts += __shfl_xor_sync(0xffffffffu, ts, 8);
            l_i[ii] = l_i[ii]*corr[ii] + ts;
        }
        // rescale O accumulators (packed row-pairs)
        #pragma unroll
        for (int a = 0; a < 4; a++) {
            unsigned long long c2 = pack2(corr[2*a], corr[2*a+1]);
            #pragma unroll
            for (int d = 0; d < 4; d++) o2[a][d] = mul2(o2[a][d], c2);
        }
        // store P transposed: psT[j][i]
        #pragma unroll
        for (int jj = 0; jj < 4; jj++)
            #pragma unroll
            for (int ii = 0; ii < 8; ii++)
                psT[(tx*4+jj)*132 + ty*8 + ii] = sc[ii][jj];
        __syncthreads();

        // ---- O += P @ V : reduce over j ----
        #pragma unroll 4
        for (int j = 0; j < 64; j++) {
            ulonglong2 pa = *(const ulonglong2*)&psT[j*132 + ty*8];
            ulonglong2 pb = *(const ulonglong2*)&psT[j*132 + ty*8 + 4];
            float4 vf = *(const float4*)&vs[j*68 + tx*4];
            unsigned long long v0 = pack2(vf.x, vf.x);
            unsigned long long v1 = pack2(vf.y, vf.y);
            unsigned long long v2 = pack2(vf.z, vf.z);
            unsigned long long v3 = pack2(vf.w, vf.w);
            fma2(o2[0][0], pa.x, v0);  fma2(o2[0][1], pa.x, v1);
            fma2(o2[0][2], pa.x, v2);  fma2(o2[0][3], pa.x, v3);
            fma2(o2[1][0], pa.y, v0);  fma2(o2[1][1], pa.y, v1);
            fma2(o2[1][2], pa.y, v2);  fma2(o2[1][3], pa.y, v3);
            fma2(o2[2][0], pb.x, v0);  fma2(o2[2][1], pb.x, v1);
            fma2(o2[2][2], pb.x, v2);  fma2(o2[2][3], pb.x, v3);
            fma2(o2[3][0], pb.y, v0);  fma2(o2[3][1], pb.y, v1);
            fma2(o2[3][2], pb.y, v2);  fma2(o2[3][3], pb.y, v3);
        }
    }

    // ---- epilogue ----
    float* Ob = O + (size_t)(b*SEQ + q0)*DMODEL + h*HD;
    #pragma unroll
    for (int a = 0; a < 4; a++) {
        float lo[4], hi[4];
        #pragma unroll
        for (int d = 0; d < 4; d++) unpack2(o2[a][d], lo[d], hi[d]);
        float inv0 = 1.f / l_i[2*a];
        float inv1 = 1.f / l_i[2*a+1];
        float4 f0, f1;
        f0.x = lo[0]*inv0; f0.y = lo[1]*inv0; f0.z = lo[2]*inv0; f0.w = lo[3]*inv0;
        f1.x = hi[0]*inv1; f1.y = hi[1]*inv1; f1.z = hi[2]*inv1; f1.w = hi[3]*inv1;
        *(float4*)&Ob[(size_t)(ty*8 + 2*a    )*DMODEL + tx*4] = f0;
        *(float4*)&Ob[(size_t)(ty*8 + 2*a + 1)*DMODEL + tx*4] = f1;
    }
}

// ---------------- launch ----------------
extern "C" void kernel_launch(void* const* d_in, const int* in_sizes, int n_in,
                              void* d_out, int out_size) {
    const float* x   = (const float*)d_in[0];
    const float* cs  = (const float*)d_in[1];
    const float* sn  = (const float*)d_in[2];
    const float* wq  = (const float*)d_in[3];
    const float* wk  = (const float*)d_in[4];
    const float* wv  = (const float*)d_in[5];
    const float* wo  = (const float*)d_in[6];
    const float* gq  = (const float*)d_in[7];
    const float* gk  = (const float*)d_in[8];
    const float* gv  = (const float*)d_in[9];
    const float* go  = (const float*)d_in[10];
    float* out = (float*)d_out;

    signed char *wq_q, *wk_q, *wv_q, *wo_q, *xq0, *xq1, *xq2, *xqo;
    float *xs0, *xs1, *xs2, *xso, *projq, *projk, *projv, *attnb;
    cudaGetSymbolAddress((void**)&wq_q, g_wq);
    cudaGetSymbolAddress((void**)&wk_q, g_wk);
    cudaGetSymbolAddress((void**)&wv_q, g_wv);
    cudaGetSymbolAddress((void**)&wo_q, g_wo);
    cudaGetSymbolAddress((void**)&xq0, g_xq0);
    cudaGetSymbolAddress((void**)&xq1, g_xq1);
    cudaGetSymbolAddress((void**)&xq2, g_xq2);
    cudaGetSymbolAddress((void**)&xqo, g_xqo);
    cudaGetSymbolAddress((void**)&xs0, g_xs0);
    cudaGetSymbolAddress((void**)&xs1, g_xs1);
    cudaGetSymbolAddress((void**)&xs2, g_xs2);
    cudaGetSymbolAddress((void**)&xso, g_xso);
    cudaGetSymbolAddress((void**)&projq, g_projq);
    cudaGetSymbolAddress((void**)&projk, g_projk);
    cudaGetSymbolAddress((void**)&projv, g_projv);
    cudaGetSymbolAddress((void**)&attnb, g_attn);

    cudaFuncSetAttribute(attn_kernel, cudaFuncAttributeMaxDynamicSharedMemorySize, 102400);
    cudaFuncSetAttribute(gemm_qkv, cudaFuncAttributeMaxDynamicSharedMemorySize, 65536);
    cudaFuncSetAttribute(gemm_imma, cudaFuncAttributeMaxDynamicSharedMemorySize, 65536);

    // weight scales + ternary quant (fused launches)
    absum_all<<<dim3(256, 4), 256>>>(wq, wk, wv, wo);
    finalize_wscale<<<1, 256>>>();
    quant_all<<<dim3(1024, 4), 256>>>(wq, wk, wv, wo, wq_q, wk_q, wv_q, wo_q);

    // activation quant (3 projections share x row + rmsnorm stat)
    act_quant<<<NTOK, 256>>>(x, gq, gk, gv, xq0, xq1, xq2, xs0, xs1, xs2);

    // projections: fused Q/K/V int8 tensor GEMM in one launch (cp.async pipelined)
    gemm_qkv<<<dim3(24, NTOK/128), 256, 65536>>>(xq0, xq1, xq2, wq_q, wk_q, wv_q,
                                                 xs0, xs1, xs2, projq, projk, projv);

    // rope (q + k fused)
    rope_all<<<(NTOK*(NH+NKV)*32)/256, 256>>>(projq, projk, cs, sn);

    // attention
    attn_kernel<<<dim3(SEQ/128, NH, BATCH), 256, 102400>>>(projq, projk, projv, attnb);

    // output bitlinear
    act_quant<<<NTOK, 256>>>(attnb, go, nullptr, nullptr, xqo, nullptr, nullptr, xso, nullptr, nullptr);
    gemm_imma<<<dim3(DMODEL/128, NTOK/128), 256, 65536>>>(xqo, wo_q, xso, 3, out, DMODEL);
}